// round 7
// baseline (speedup 1.0000x reference)
#include <cuda_runtime.h>
#include <math.h>

// ---------------------------------------------------------------------------
// Fused NeRF MLP, fp32, f32x2 FMA + SMEM-staged weights (double-buffered
// cp.async). N=131072, W=256. Per CTA: 64 rows, 512 threads.
// Activations in SMEM: [64][344] = [e_pts(84) | h(256)] -> skip concat free.
// Output: d_out[0..N) = alpha, d_out[N..4N) = rgb row-major [N,3].
// ---------------------------------------------------------------------------

#define NPTS   131072
#define MTILE  64
#define NTH    512
#define HSTR   344
#define EVSTR  56
#define KC     32          // k-rows per staged weight tile

// ---- f32x2 packed helpers ---------------------------------------------------
__device__ __forceinline__ unsigned long long pk2(float lo, float hi) {
    unsigned long long r;
    asm("mov.b64 %0, {%1,%2};" : "=l"(r)
        : "r"(__float_as_uint(lo)), "r"(__float_as_uint(hi)));
    return r;
}
__device__ __forceinline__ void upk2(unsigned long long v, float& lo, float& hi) {
    unsigned int l, h;
    asm("mov.b64 {%0,%1}, %2;" : "=r"(l), "=r"(h) : "l"(v));
    lo = __uint_as_float(l);
    hi = __uint_as_float(h);
}
__device__ __forceinline__ unsigned long long ffma2(unsigned long long a,
                                                    unsigned long long b,
                                                    unsigned long long c) {
    unsigned long long d;
    asm("fma.rn.f32x2 %0, %1, %2, %3;" : "=l"(d) : "l"(a), "l"(b), "l"(c));
    return d;
}

// ---- cp.async helpers -------------------------------------------------------
__device__ __forceinline__ void cp_async16(float* sdst, const float* gsrc) {
    unsigned s = (unsigned)__cvta_generic_to_shared(sdst);
    asm volatile("cp.async.cg.shared.global [%0], [%1], 16;" :: "r"(s), "l"(gsrc));
}
__device__ __forceinline__ void cp_commit() {
    asm volatile("cp.async.commit_group;");
}
template<int N>
__device__ __forceinline__ void cp_wait() {
    asm volatile("cp.async.wait_group %0;" :: "n"(N));
}

// ---------------------------------------------------------------------------
// dense with SMEM weight staging.
//   sm_out[64][OUT] = act( sm_in[64][K] @ W[K][OUT] + B )
// OUT=256 -> RPT=4 (32 col-groups x 16 row-groups, 512 thr)
// OUT=128 -> RPT=2 (16 col-groups x 32 row-groups)
// wbuf: 2 * KC * OUT floats (double buffer).
// ---------------------------------------------------------------------------
template<int OUT, int RPT>
__device__ __noinline__ void dense(const float* __restrict__ sm_in, int in_stride, int K,
                                   const float* __restrict__ W, const float* __restrict__ B,
                                   float* __restrict__ sm_out, int out_stride, bool do_relu,
                                   float* __restrict__ wbuf)
{
    constexpr int CG = OUT / 8;
    const int tid = threadIdx.x;
    const int j0  = (tid % CG) * 8;
    const int r0  = (tid / CG) * RPT;

    unsigned long long acc[RPT][4];
    {
        float4 bA = *reinterpret_cast<const float4*>(B + j0);
        float4 bB = *reinterpret_cast<const float4*>(B + j0 + 4);
        unsigned long long p0 = pk2(bA.x, bA.y), p1 = pk2(bA.z, bA.w);
        unsigned long long p2 = pk2(bB.x, bB.y), p3 = pk2(bB.z, bB.w);
        #pragma unroll
        for (int r = 0; r < RPT; r++) {
            acc[r][0] = p0; acc[r][1] = p1; acc[r][2] = p2; acc[r][3] = p3;
        }
    }

    const int nT = (K + KC - 1) / KC;

    // prologue: stage tile 0
    {
        int rows = (K < KC) ? K : KC;
        int total = rows * OUT;
        const float* src = W;
        float* dst = wbuf;
        for (int idx = tid * 4; idx < total; idx += NTH * 4)
            cp_async16(dst + idx, src + idx);
        cp_commit();
    }

    #pragma unroll 1
    for (int t = 0; t < nT; t++) {
        if (t + 1 < nT) {
            int rows = K - (t + 1) * KC; if (rows > KC) rows = KC;
            int total = rows * OUT;
            const float* src = W + (size_t)(t + 1) * KC * OUT;
            float* dst = wbuf + ((t + 1) & 1) * (KC * OUT);
            for (int idx = tid * 4; idx < total; idx += NTH * 4)
                cp_async16(dst + idx, src + idx);
            cp_commit();
            cp_wait<1>();
        } else {
            cp_wait<0>();
        }
        __syncthreads();   // tile t visible to all

        const float* wb_ = wbuf + (t & 1) * (KC * OUT);
        const int kbase = t * KC;
        int rows = K - kbase; if (rows > KC) rows = KC;
        const int rmain = rows & ~3;

        int kk = 0;
        #pragma unroll 2
        for (; kk < rmain; kk += 4) {
            unsigned long long w[4][4];
            #pragma unroll
            for (int q = 0; q < 4; q++) {
                const double2* wp =
                    reinterpret_cast<const double2*>(wb_ + (kk + q) * OUT + j0);
                double2 wa = wp[0];
                double2 wbv = wp[1];
                w[q][0] = __double_as_longlong(wa.x);
                w[q][1] = __double_as_longlong(wa.y);
                w[q][2] = __double_as_longlong(wbv.x);
                w[q][3] = __double_as_longlong(wbv.y);
            }
            #pragma unroll
            for (int r = 0; r < RPT; r++) {
                float4 h4 = *reinterpret_cast<const float4*>(
                    sm_in + (r0 + r) * in_stride + kbase + kk);
                unsigned long long hd;
                hd = pk2(h4.x, h4.x);
                acc[r][0] = ffma2(hd, w[0][0], acc[r][0]);
                acc[r][1] = ffma2(hd, w[0][1], acc[r][1]);
                acc[r][2] = ffma2(hd, w[0][2], acc[r][2]);
                acc[r][3] = ffma2(hd, w[0][3], acc[r][3]);
                hd = pk2(h4.y, h4.y);
                acc[r][0] = ffma2(hd, w[1][0], acc[r][0]);
                acc[r][1] = ffma2(hd, w[1][1], acc[r][1]);
                acc[r][2] = ffma2(hd, w[1][2], acc[r][2]);
                acc[r][3] = ffma2(hd, w[1][3], acc[r][3]);
                hd = pk2(h4.z, h4.z);
                acc[r][0] = ffma2(hd, w[2][0], acc[r][0]);
                acc[r][1] = ffma2(hd, w[2][1], acc[r][1]);
                acc[r][2] = ffma2(hd, w[2][2], acc[r][2]);
                acc[r][3] = ffma2(hd, w[2][3], acc[r][3]);
                hd = pk2(h4.w, h4.w);
                acc[r][0] = ffma2(hd, w[3][0], acc[r][0]);
                acc[r][1] = ffma2(hd, w[3][1], acc[r][1]);
                acc[r][2] = ffma2(hd, w[3][2], acc[r][2]);
                acc[r][3] = ffma2(hd, w[3][3], acc[r][3]);
            }
        }
        // scalar tail (views layer K=310: last tile rows=22 -> 2 tail rows)
        for (; kk < rows; kk++) {
            const double2* wp = reinterpret_cast<const double2*>(wb_ + kk * OUT + j0);
            double2 wa = wp[0];
            double2 wbv = wp[1];
            unsigned long long w0 = __double_as_longlong(wa.x);
            unsigned long long w1 = __double_as_longlong(wa.y);
            unsigned long long w2 = __double_as_longlong(wbv.x);
            unsigned long long w3 = __double_as_longlong(wbv.y);
            #pragma unroll
            for (int r = 0; r < RPT; r++) {
                float h = sm_in[(r0 + r) * in_stride + kbase + kk];
                unsigned long long hd = pk2(h, h);
                acc[r][0] = ffma2(hd, w0, acc[r][0]);
                acc[r][1] = ffma2(hd, w1, acc[r][1]);
                acc[r][2] = ffma2(hd, w2, acc[r][2]);
                acc[r][3] = ffma2(hd, w3, acc[r][3]);
            }
        }
        __syncthreads();   // compute of tile t done before buffer reuse / output
    }

    // write out (tile loop's trailing barrier ordered all sm_in reads)
    #pragma unroll
    for (int r = 0; r < RPT; r++) {
        float o[8];
        upk2(acc[r][0], o[0], o[1]);
        upk2(acc[r][1], o[2], o[3]);
        upk2(acc[r][2], o[4], o[5]);
        upk2(acc[r][3], o[6], o[7]);
        if (do_relu) {
            #pragma unroll
            for (int i = 0; i < 8; i++) o[i] = fmaxf(o[i], 0.0f);
        }
        float* op = sm_out + (r0 + r) * out_stride + j0;
        *reinterpret_cast<float4*>(op)     = make_float4(o[0], o[1], o[2], o[3]);
        *reinterpret_cast<float4*>(op + 4) = make_float4(o[4], o[5], o[6], o[7]);
    }
    __syncthreads();
}

struct KParams {
    const float *input_pts, *input_views, *input_pls;
    const float *pw[8], *pb[8];
    const float *views_w, *views_b;
    const float *feature_w, *feature_b;
    const float *alpha_w, *alpha_b;
    const float *rgb_w, *rgb_b;
    float *out;
};

extern __shared__ float smem[];

__global__ void __launch_bounds__(NTH, 1) nerf_fused(KParams P)
{
    float* sm_h  = smem;                            // [64][344]
    float* sm_ev = smem + MTILE * HSTR;             // [64][56]
    float* sm_hv = sm_ev + MTILE * EVSTR;           // [64][128]
    float* sm_w  = sm_hv + MTILE * 128;             // [2][KC*256]

    const int tid = threadIdx.x;
    const int blk = blockIdx.x;

    // ---- positional encodings ---------------------------------------------
    if (tid < MTILE) {
        const int g = blk * MTILE + tid;
        float4 p = *reinterpret_cast<const float4*>(P.input_pts + (size_t)g * 4);
        float* row = sm_h + tid * HSTR;
        float xs[4] = {p.x, p.y, p.z, p.w};
        #pragma unroll
        for (int d = 0; d < 4; d++) row[d] = xs[d];
        #pragma unroll
        for (int d = 0; d < 4; d++) {
            float f = 1.0f;
            #pragma unroll
            for (int l = 0; l < 10; l++) {
                float s, c;
                sincosf(xs[d] * f, &s, &c);
                row[4 + d * 20 + l * 2]     = s;
                row[4 + d * 20 + l * 2 + 1] = c;
                f *= 2.0f;
            }
        }
    } else if (tid < 2 * MTILE) {
        const int r = tid - MTILE;
        const int g = blk * MTILE + r;
        float xs[6];
        xs[0] = P.input_views[(size_t)g * 3 + 0];
        xs[1] = P.input_views[(size_t)g * 3 + 1];
        xs[2] = P.input_views[(size_t)g * 3 + 2];
        xs[3] = P.input_pls[(size_t)g * 3 + 0];
        xs[4] = P.input_pls[(size_t)g * 3 + 1];
        xs[5] = P.input_pls[(size_t)g * 3 + 2];
        float* row = sm_ev + r * EVSTR;
        #pragma unroll
        for (int d = 0; d < 6; d++) row[d] = xs[d];
        #pragma unroll
        for (int d = 0; d < 6; d++) {
            float f = 1.0f;
            #pragma unroll
            for (int l = 0; l < 4; l++) {
                float s, c;
                sincosf(xs[d] * f, &s, &c);
                row[6 + d * 8 + l * 2]     = s;
                row[6 + d * 8 + l * 2 + 1] = c;
                f *= 2.0f;
            }
        }
    }
    __syncthreads();

    // ---- pts MLP ------------------------------------------------------------
    dense<256, 4>(sm_h, HSTR, 84, P.pw[0], P.pb[0], sm_h + 84, HSTR, true, sm_w);
    #pragma unroll 1
    for (int i = 1; i <= 4; i++)
        dense<256, 4>(sm_h + 84, HSTR, 256, P.pw[i], P.pb[i], sm_h + 84, HSTR, true, sm_w);
    dense<256, 4>(sm_h, HSTR, 340, P.pw[5], P.pb[5], sm_h + 84, HSTR, true, sm_w);
    dense<256, 4>(sm_h + 84, HSTR, 256, P.pw[6], P.pb[6], sm_h + 84, HSTR, true, sm_w);
    dense<256, 4>(sm_h + 84, HSTR, 256, P.pw[7], P.pb[7], sm_h + 84, HSTR, true, sm_w);

    // ---- alpha head (reads h before feature overwrites cols [0..256)) ------
    if (tid < MTILE) {
        const float* hr = sm_h + tid * HSTR + 84;
        float a = P.alpha_b[0];
        #pragma unroll 4
        for (int kk = 0; kk < 256; kk += 4) {
            float4 h4 = *reinterpret_cast<const float4*>(hr + kk);
            float4 w4 = *reinterpret_cast<const float4*>(P.alpha_w + kk);
            a += h4.x * w4.x + h4.y * w4.y + h4.z * w4.z + h4.w * w4.w;
        }
        P.out[blk * MTILE + tid] = a;
    }

    // ---- feature (no relu) -> cols [0..256) ---------------------------------
    dense<256, 4>(sm_h + 84, HSTR, 256, P.feature_w, P.feature_b, sm_h, HSTR, false, sm_w);

    // ---- append e_view at cols [256..310) -----------------------------------
    for (int idx = tid; idx < MTILE * 54; idx += NTH) {
        int r = idx / 54;
        int c = idx - r * 54;
        sm_h[r * HSTR + 256 + c] = sm_ev[r * EVSTR + c];
    }
    __syncthreads();

    // ---- views layer: [feature|e_view](310) -> hv(128), relu ----------------
    dense<128, 2>(sm_h, HSTR, 310, P.views_w, P.views_b, sm_hv, 128, true, sm_w);

    // ---- rgb head ------------------------------------------------------------
    if (tid < MTILE * 3) {
        int r = tid / 3;
        int c = tid - r * 3;
        const float* hv = sm_hv + r * 128;
        float a = P.rgb_b[c];
        #pragma unroll 8
        for (int kk = 0; kk < 128; kk++) a += hv[kk] * P.rgb_w[kk * 3 + c];
        P.out[(size_t)NPTS + (size_t)(blk * MTILE + r) * 3 + c] = a;
    }
}

extern "C" void kernel_launch(void* const* d_in, const int* in_sizes, int n_in,
                              void* d_out, int out_size)
{
    (void)in_sizes; (void)n_in; (void)out_size;
    KParams P;
    P.input_pts   = (const float*)d_in[0];
    P.input_views = (const float*)d_in[1];
    P.input_pls   = (const float*)d_in[2];
    for (int i = 0; i < 8; i++) {
        P.pw[i] = (const float*)d_in[3 + 2 * i];
        P.pb[i] = (const float*)d_in[4 + 2 * i];
    }
    P.views_w   = (const float*)d_in[19];
    P.views_b   = (const float*)d_in[20];
    P.feature_w = (const float*)d_in[21];
    P.feature_b = (const float*)d_in[22];
    P.alpha_w   = (const float*)d_in[23];
    P.alpha_b   = (const float*)d_in[24];
    P.rgb_w     = (const float*)d_in[25];
    P.rgb_b     = (const float*)d_in[26];
    P.out       = (float*)d_out;

    const int smem_bytes =
        (MTILE * HSTR + MTILE * EVSTR + MTILE * 128 + 2 * KC * 256) * (int)sizeof(float);
    cudaFuncSetAttribute(nerf_fused, cudaFuncAttributeMaxDynamicSharedMemorySize, smem_bytes);
    nerf_fused<<<NPTS / MTILE, NTH, smem_bytes>>>(P);
}

// round 9
// speedup vs baseline: 4.1262x; 4.1262x over previous
#include <cuda_runtime.h>
#include <cuda_bf16.h>
#include <cstdint>
#include <math.h>

// ============================================================================
// NeRF fused MLP via mma.sync (HMMA, base sm_103 target), 3-term bf16 split.
// Per CTA: 128 rows, 512 threads (16 warps, 4Mx4N).
// A (activations) hi/lo bf16 planes in SMEM [128][360]:
//   cols 0..83 e_pts, 84..95 zero, 96..351 h   -> skip concat free.
// Weights pre-split into 160 uniform chunks (16 k-rows x 264 cols, hi+lo) in
// g_wbuf, consumption order; streamed with double-buffered cp.async.
// Output: d_out[0..N) = alpha, d_out[N..4N) = rgb row-major [N,3].
// ============================================================================

#define NPTS  131072
#define NTH   512
#define NBLK  (NPTS / 128)

// ---- smem byte offsets -------------------------------------------------------
#define A_HI   0u
#define A_LO   92160u
#define ASTR   720u          // 360 bf16 per row
#define WB0    184320u
#define WB1    201216u
#define WLO    8448u         // lo plane offset inside a W tile
#define WSTR   528u          // 264 bf16 per W row
#define PRGB   184320u       // rgb partials overlay WB0 (weights dead by then)
#define APAD   704u          // alpha partials: A_HI row pad bytes [704..720)
#define SMEM_REQ 218112
#define NCHTOT 160
#define CHB    16896u        // bytes per weight chunk (hi+lo)

__device__ __align__(16) __nv_bfloat16 g_wbuf[1351680];   // 160 * CHB bytes

// ---- small helpers -------------------------------------------------------------
__device__ __forceinline__ uint32_t smem_u32(const void* p) {
    uint32_t a;
    asm("{ .reg .u64 t; cvta.to.shared.u64 t, %1; cvt.u32.u64 %0, t; }"
        : "=r"(a) : "l"(p));
    return a;
}
__device__ __forceinline__ void cp_async16(uint32_t saddr, const void* g) {
    asm volatile("cp.async.cg.shared.global [%0], [%1], 16;" :: "r"(saddr), "l"(g));
}
__device__ __forceinline__ void cp_commit() { asm volatile("cp.async.commit_group;"); }
__device__ __forceinline__ void cp_wait1() {
    asm volatile("cp.async.wait_group 1;" ::: "memory");
}
__device__ __forceinline__ void ldm4(uint32_t d[4], uint32_t a) {
    asm volatile("ldmatrix.sync.aligned.m8n8.x4.shared.b16 {%0,%1,%2,%3}, [%4];"
        : "=r"(d[0]), "=r"(d[1]), "=r"(d[2]), "=r"(d[3]) : "r"(a));
}
__device__ __forceinline__ void ldm4t(uint32_t d[4], uint32_t a) {
    asm volatile("ldmatrix.sync.aligned.m8n8.x4.trans.shared.b16 {%0,%1,%2,%3}, [%4];"
        : "=r"(d[0]), "=r"(d[1]), "=r"(d[2]), "=r"(d[3]) : "r"(a));
}
__device__ __forceinline__ void mma16816(float c[4], const uint32_t a[4],
                                         uint32_t b0, uint32_t b1) {
    asm volatile("mma.sync.aligned.m16n8k16.row.col.f32.bf16.bf16.f32 "
        "{%0,%1,%2,%3}, {%4,%5,%6,%7}, {%8,%9}, {%0,%1,%2,%3};"
        : "+f"(c[0]), "+f"(c[1]), "+f"(c[2]), "+f"(c[3])
        : "r"(a[0]), "r"(a[1]), "r"(a[2]), "r"(a[3]), "r"(b0), "r"(b1));
}
__device__ __forceinline__ uint32_t pack_bf2(float a, float b) {
    __nv_bfloat162 t = __floats2bfloat162_rn(a, b);
    return *reinterpret_cast<uint32_t*>(&t);
}
__device__ __forceinline__ float bhi(float x) {
    return __bfloat162float(__float2bfloat16(x));
}

// ============================================================================
// prep: fp32 weights -> hi/lo bf16, K-padded, chunk-sequential [k][264] planes
// ============================================================================
struct PrepP { const float* w[10]; };   // pw0..7, feature_w, views_w

__global__ void prep_kernel(PrepP pp) {
    const int cum[11] = {0,6,22,38,54,70,92,108,124,140,160};
    for (unsigned e = blockIdx.x * blockDim.x + threadIdx.x; e < 675840u;
         e += gridDim.x * blockDim.x) {
        unsigned g = e / 4224u, rem = e - g * 4224u;
        unsigned r = rem / 264u, c = rem - r * 264u;
        int l = 9;
        for (int i = 1; i <= 9; i++) { if ((int)g < cum[i]) { l = i - 1; break; } }
        int krow = (int)(g - cum[l]) * 16 + (int)r;
        int N = (l == 9) ? 128 : 256;
        int sr = krow;
        if (l == 0)      sr = (krow < 84)  ? krow : -1;
        else if (l == 5) sr = (krow < 84)  ? krow : (krow < 96 ? -1 : krow - 12);
        else if (l == 9) sr = (krow < 310) ? krow : -1;
        float v = 0.f;
        if (sr >= 0 && (int)c < N) v = pp.w[l][(size_t)sr * N + c];
        __nv_bfloat16 hb = __float2bfloat16(v);
        __nv_bfloat16 lb = __float2bfloat16(v - __bfloat162float(hb));
        char* p = (char*)g_wbuf + (size_t)g * CHB + r * WSTR + c * 2u;
        *(__nv_bfloat16*)p = hb;
        *(__nv_bfloat16*)(p + WLO) = lb;
    }
}

// ============================================================================
// chunk compute: acc += A[128, k16] * W[k16, N]  (3-term split)
// ============================================================================
template<int N8>
__device__ __forceinline__ void chunk_mma(uint32_t base32, uint32_t wtile,
                                          int wm, int wn, int lane,
                                          int kcol, float acc[2][8][4]) {
    const uint32_t arow = (uint32_t)(wm * 32 + (lane & 15));
    const uint32_t acol = (uint32_t)kcol + (uint32_t)((lane >> 4) << 3);
    uint32_t a0 = base32 + A_HI + arow * ASTR + acol * 2u;
    uint32_t a1 = a0 + 16u * ASTR;
    uint32_t ahi[2][4], alo[2][4], b[N8 / 2][4];
    ldm4(ahi[0], a0); ldm4(ahi[1], a1);
    ldm4(alo[0], a0 + A_LO); ldm4(alo[1], a1 + A_LO);
    const uint32_t nw = (N8 == 8) ? 64u : 32u;
    uint32_t wb = wtile + (uint32_t)(lane & 15) * WSTR
                + ((uint32_t)wn * nw + (uint32_t)((lane >> 4) << 3)) * 2u;
    #pragma unroll
    for (int g2 = 0; g2 < N8 / 2; g2++) ldm4t(b[g2], wb + g2 * 32u);
    #pragma unroll
    for (int mt = 0; mt < 2; mt++)
        #pragma unroll
        for (int n8 = 0; n8 < N8; n8++)
            mma16816(acc[mt][n8], ahi[mt], b[n8 >> 1][(n8 & 1) * 2], b[n8 >> 1][(n8 & 1) * 2 + 1]);
    #pragma unroll
    for (int mt = 0; mt < 2; mt++)
        #pragma unroll
        for (int n8 = 0; n8 < N8; n8++)
            mma16816(acc[mt][n8], alo[mt], b[n8 >> 1][(n8 & 1) * 2], b[n8 >> 1][(n8 & 1) * 2 + 1]);
    #pragma unroll
    for (int g2 = 0; g2 < N8 / 2; g2++) ldm4t(b[g2], wb + WLO + g2 * 32u);
    #pragma unroll
    for (int mt = 0; mt < 2; mt++)
        #pragma unroll
        for (int n8 = 0; n8 < N8; n8++)
            mma16816(acc[mt][n8], ahi[mt], b[n8 >> 1][(n8 & 1) * 2], b[n8 >> 1][(n8 & 1) * 2 + 1]);
}

// ============================================================================
struct MainP {
    const float *input_pts, *input_views, *input_pls;
    const float *bias[9];          // pb0..7, feature_b
    const float *views_b;
    const float *alpha_w, *alpha_b;
    const float *rgb_w, *rgb_b;
    float* out;
};

extern __shared__ char smdyn[];

__global__ void __launch_bounds__(NTH, 1) nerf_hmma(MainP P) {
    char* sm = smdyn;
    const uint32_t base32 = smem_u32(sm);
    const int tid = threadIdx.x, lane = tid & 31, wid = tid >> 5;
    const int wm = wid >> 2, wn = wid & 3;
    const int blk = blockIdx.x;

    // prologue: prefetch weight chunk 0
    for (uint32_t off = tid * 16u; off < CHB; off += NTH * 16u)
        cp_async16(base32 + WB0 + off, (const char*)g_wbuf + off);
    cp_commit();

    // e_pts build: cols 0..83, pad 84..95 zero
    if (tid < 128) {
        size_t gidx = (size_t)blk * 128 + tid;
        float4 p4 = *reinterpret_cast<const float4*>(P.input_pts + gidx * 4);
        float xs[4] = {p4.x, p4.y, p4.z, p4.w};
        float vals[96];
        #pragma unroll
        for (int d = 0; d < 4; d++) vals[d] = xs[d];
        #pragma unroll
        for (int d = 0; d < 4; d++) {
            float f = 1.f;
            #pragma unroll
            for (int l = 0; l < 10; l++) {
                float sn, cs; sincosf(xs[d] * f, &sn, &cs);
                vals[4 + d * 20 + l * 2]     = sn;
                vals[4 + d * 20 + l * 2 + 1] = cs;
                f *= 2.f;
            }
        }
        #pragma unroll
        for (int k = 84; k < 96; k++) vals[k] = 0.f;
        char* rh = sm + A_HI + (uint32_t)tid * ASTR;
        #pragma unroll 4
        for (int k = 0; k < 96; k += 2) {
            float f0 = vals[k], f1 = vals[k + 1];
            *(uint32_t*)(rh + k * 2)        = pack_bf2(f0, f1);
            *(uint32_t*)(rh + A_LO + k * 2) = pack_bf2(f0 - bhi(f0), f1 - bhi(f1));
        }
    }

    const int L_koff[9] = {0, 96, 96, 96, 96, 0, 96, 96, 96};
    const int L_nch[9]  = {6, 16, 16, 16, 16, 22, 16, 16, 16};
    float acc[2][8][4];
    int g = 0;

    #pragma unroll 1
    for (int l = 0; l < 9; l++) {
        #pragma unroll
        for (int mt = 0; mt < 2; mt++)
            #pragma unroll
            for (int n8 = 0; n8 < 8; n8++)
                #pragma unroll
                for (int q = 0; q < 4; q++) acc[mt][n8][q] = 0.f;

        const int koff = L_koff[l], nch = L_nch[l];
        #pragma unroll 1
        for (int ch = 0; ch < nch; ch++) {
            __syncthreads();                               // buffer reuse guard
            if (g + 1 < NCHTOT) {
                uint32_t dst = base32 + (((g + 1) & 1) ? WB1 : WB0);
                const char* src = (const char*)g_wbuf + (size_t)(g + 1) * CHB;
                for (uint32_t off = tid * 16u; off < CHB; off += NTH * 16u)
                    cp_async16(dst + off, src + off);
            }
            cp_commit();
            cp_wait1();                                    // chunk g landed
            __syncthreads();                               // visible to all
            chunk_mma<8>(base32, base32 + ((g & 1) ? WB1 : WB0),
                         wm, wn, lane, koff + ch * 16, acc);
            g++;
        }
        __syncthreads();                                   // all mma done before A writes

        // ---- epilogue: bias (+relu) (+alpha) -> split -> A hi/lo -------------
        const bool relu = (l != 8);
        const uint32_t colbase = (l == 8) ? 0u : 96u;
        const float* bias = P.bias[l];
        float ap[2][2] = {{0.f, 0.f}, {0.f, 0.f}};
        #pragma unroll
        for (int mt = 0; mt < 2; mt++) {
            #pragma unroll
            for (int half = 0; half < 2; half++) {
                const uint32_t row = (uint32_t)(wm * 32 + mt * 16 + half * 8 + (lane >> 2));
                char* rh = sm + A_HI + row * ASTR + colbase * 2u;
                #pragma unroll
                for (int n8 = 0; n8 < 8; n8++) {
                    const int col = wn * 64 + n8 * 8 + (lane & 3) * 2;
                    float2 bv = *(const float2*)(bias + col);
                    float f0 = acc[mt][n8][half * 2]     + bv.x;
                    float f1 = acc[mt][n8][half * 2 + 1] + bv.y;
                    if (relu) { f0 = fmaxf(f0, 0.f); f1 = fmaxf(f1, 0.f); }
                    if (l == 7) {
                        float2 aw = *(const float2*)(P.alpha_w + col);
                        ap[mt][half] += f0 * aw.x + f1 * aw.y;
                    }
                    *(uint32_t*)(rh + col * 2)        = pack_bf2(f0, f1);
                    *(uint32_t*)(rh + A_LO + col * 2) = pack_bf2(f0 - bhi(f0), f1 - bhi(f1));
                }
            }
        }
        if (l == 7) {        // alpha partials -> A_HI row pad
            #pragma unroll
            for (int mt = 0; mt < 2; mt++)
                #pragma unroll
                for (int half = 0; half < 2; half++) {
                    float v = ap[mt][half];
                    v += __shfl_xor_sync(0xffffffffu, v, 1);
                    v += __shfl_xor_sync(0xffffffffu, v, 2);
                    if ((lane & 3) == 0) {
                        uint32_t row = (uint32_t)(wm * 32 + mt * 16 + half * 8 + (lane >> 2));
                        *(float*)(sm + A_HI + row * ASTR + APAD + wn * 4) = v;
                    }
                }
            __syncthreads();
            if (tid < 128) {
                char* rp = sm + A_HI + (uint32_t)tid * ASTR + APAD;
                float a = P.alpha_b[0];
                #pragma unroll
                for (int w = 0; w < 4; w++) a += *(float*)(rp + w * 4);
                P.out[(size_t)blk * 128 + tid] = a;
            }
        }
        if (l == 8 && tid < 128) {   // e_view into cols 256..319 (310..319 zero)
            size_t gidx = (size_t)blk * 128 + tid;
            float xs[6];
            xs[0] = P.input_views[gidx * 3];     xs[1] = P.input_views[gidx * 3 + 1];
            xs[2] = P.input_views[gidx * 3 + 2]; xs[3] = P.input_pls[gidx * 3];
            xs[4] = P.input_pls[gidx * 3 + 1];   xs[5] = P.input_pls[gidx * 3 + 2];
            float vals[64];
            #pragma unroll
            for (int d = 0; d < 6; d++) vals[d] = xs[d];
            #pragma unroll
            for (int d = 0; d < 6; d++) {
                float f = 1.f;
                #pragma unroll
                for (int q = 0; q < 4; q++) {
                    float sn, cs; sincosf(xs[d] * f, &sn, &cs);
                    vals[6 + d * 8 + q * 2]     = sn;
                    vals[6 + d * 8 + q * 2 + 1] = cs;
                    f *= 2.f;
                }
            }
            #pragma unroll
            for (int k = 54; k < 64; k++) vals[k] = 0.f;
            char* rh = sm + A_HI + (uint32_t)tid * ASTR + 256u * 2u;
            #pragma unroll 4
            for (int k = 0; k < 64; k += 2) {
                float f0 = vals[k], f1 = vals[k + 1];
                *(uint32_t*)(rh + k * 2)        = pack_bf2(f0, f1);
                *(uint32_t*)(rh + A_LO + k * 2) = pack_bf2(f0 - bhi(f0), f1 - bhi(f1));
            }
        }
    }

    // ---- views layer: K=320, N=128 -------------------------------------------
    #pragma unroll
    for (int mt = 0; mt < 2; mt++)
        #pragma unroll
        for (int n8 = 0; n8 < 8; n8++)
            #pragma unroll
            for (int q = 0; q < 4; q++) acc[mt][n8][q] = 0.f;
    #pragma unroll 1
    for (int ch = 0; ch < 20; ch++) {
        __syncthreads();
        if (g + 1 < NCHTOT) {
            uint32_t dst = base32 + (((g + 1) & 1) ? WB1 : WB0);
            const char* src = (const char*)g_wbuf + (size_t)(g + 1) * CHB;
            for (uint32_t off = tid * 16u; off < CHB; off += NTH * 16u)
                cp_async16(dst + off, src + off);
        }
        cp_commit();
        cp_wait1();
        __syncthreads();
        chunk_mma<4>(base32, base32 + ((g & 1) ? WB1 : WB0), wm, wn, lane, ch * 16, acc);
        g++;
    }
    __syncthreads();

    // ---- rgb head: relu(C + views_b) . rgb_w, fp32 ----------------------------
    float rp[2][2][3] = {};
    #pragma unroll
    for (int mt = 0; mt < 2; mt++)
        #pragma unroll
        for (int half = 0; half < 2; half++)
            #pragma unroll
            for (int n8 = 0; n8 < 4; n8++) {
                const int col = wn * 32 + n8 * 8 + (lane & 3) * 2;
                float f0 = fmaxf(acc[mt][n8][half * 2]     + P.views_b[col],     0.f);
                float f1 = fmaxf(acc[mt][n8][half * 2 + 1] + P.views_b[col + 1], 0.f);
                const float* w0 = P.rgb_w + (size_t)col * 3;
                #pragma unroll
                for (int k = 0; k < 3; k++)
                    rp[mt][half][k] += f0 * w0[k] + f1 * w0[3 + k];
            }
    #pragma unroll
    for (int mt = 0; mt < 2; mt++)
        #pragma unroll
        for (int half = 0; half < 2; half++) {
            #pragma unroll
            for (int k = 0; k < 3; k++) {
                float v = rp[mt][half][k];
                v += __shfl_xor_sync(0xffffffffu, v, 1);
                v += __shfl_xor_sync(0xffffffffu, v, 2);
                rp[mt][half][k] = v;
            }
            if ((lane & 3) == 0) {
                uint32_t row = (uint32_t)(wm * 32 + mt * 16 + half * 8 + (lane >> 2));
                char* p = sm + PRGB + (row * 4 + wn) * 12;
                #pragma unroll
                for (int k = 0; k < 3; k++) *(float*)(p + k * 4) = rp[mt][half][k];
            }
        }
    __syncthreads();
    if (tid < 128) {
        float r[3] = {P.rgb_b[0], P.rgb_b[1], P.rgb_b[2]};
        char* p = sm + PRGB + (uint32_t)tid * 48;
        #pragma unroll
        for (int w = 0; w < 4; w++)
            #pragma unroll
            for (int k = 0; k < 3; k++) r[k] += *(float*)(p + w * 12 + k * 4);
        size_t gidx = (size_t)blk * 128 + tid;
        #pragma unroll
        for (int k = 0; k < 3; k++) P.out[(size_t)NPTS + gidx * 3 + k] = r[k];
    }
}

// ============================================================================
extern "C" void kernel_launch(void* const* d_in, const int* in_sizes, int n_in,
                              void* d_out, int out_size)
{
    (void)in_sizes; (void)n_in; (void)out_size;

    PrepP pp;
    for (int i = 0; i < 8; i++) pp.w[i] = (const float*)d_in[3 + 2 * i];
    pp.w[8] = (const float*)d_in[21];     // feature_w
    pp.w[9] = (const float*)d_in[19];     // views_w

    MainP P;
    P.input_pts   = (const float*)d_in[0];
    P.input_views = (const float*)d_in[1];
    P.input_pls   = (const float*)d_in[2];
    for (int i = 0; i < 8; i++) P.bias[i] = (const float*)d_in[4 + 2 * i];
    P.bias[8]  = (const float*)d_in[22];  // feature_b
    P.views_b  = (const float*)d_in[20];
    P.alpha_w  = (const float*)d_in[23];
    P.alpha_b  = (const float*)d_in[24];
    P.rgb_w    = (const float*)d_in[25];
    P.rgb_b    = (const float*)d_in[26];
    P.out      = (float*)d_out;

    prep_kernel<<<1320, 512>>>(pp);

    cudaFuncSetAttribute(nerf_hmma, cudaFuncAttributeMaxDynamicSharedMemorySize, SMEM_REQ);
    nerf_hmma<<<NBLK, NTH, SMEM_REQ>>>(P);
}

// round 10
// speedup vs baseline: 4.7559x; 1.1526x over previous
#include <cuda_runtime.h>
#include <cuda_bf16.h>
#include <cstdint>
#include <math.h>

// ============================================================================
// NeRF fused MLP via mma.sync (HMMA), 3-term bf16 split, per-group weight
// pipelines. Per CTA: 128 rows, 512 threads (16 warps).
//   wn = wid>>2 (N quarter, group id), wm = wid&3 (M quarter) -> each group's
//   4 warps land on 4 different SMSPs; each SMSP hosts one warp per group.
// Each group double-buffers ITS 64-col W slice (hi+lo) with cp.async driven
// by its diagonal loader warp (wm==wn) + named barriers -> groups drift,
// tensor pipe stays fed. Block-wide barriers only at layer boundaries.
// A (activations) hi/lo bf16 planes in SMEM [128][360]:
//   cols 0..83 e_pts (pad->95), 96..351 h  -> skip concat free.
// Output: d_out[0..N) = alpha, d_out[N..4N) = rgb row-major [N,3].
// ============================================================================

#define NPTS  131072
#define NTH   512
#define NBLK  (NPTS / 128)

// ---- smem byte offsets -------------------------------------------------------
#define A_HI   0u
#define A_LO   92160u
#define ASTR   720u          // 360 bf16 per row (704 data + 16 pad for alpha)
#define APAD   704u
#define SLB    184320u       // W slice buffers: 4 groups x 2 bufs x 4608 B
#define GRPSTR 9216u
#define BUFSTR 4608u
#define SLO    2304u         // lo plane offset inside a slice
#define SSTR   144u          // slice row stride (conflict-free ldmatrix)
#define PRGB   184320u       // rgb partials overlay slices (after full sync)
#define SMEM_REQ 221184
#define NCHTOT 160
#define CHB    16896u        // bytes per weight chunk in g_wbuf (hi+lo)
#define WLO    8448u         // lo plane offset inside a g_wbuf chunk
#define WSTRG  528u          // g_wbuf row stride (264 bf16)

__device__ __align__(16) __nv_bfloat16 g_wbuf[1351680];   // 160 * CHB bytes

// ---- helpers -------------------------------------------------------------------
__device__ __forceinline__ uint32_t smem_u32(const void* p) {
    uint32_t a;
    asm("{ .reg .u64 t; cvta.to.shared.u64 t, %1; cvt.u32.u64 %0, t; }"
        : "=r"(a) : "l"(p));
    return a;
}
__device__ __forceinline__ void cp_async16(uint32_t saddr, const void* g) {
    asm volatile("cp.async.cg.shared.global [%0], [%1], 16;" :: "r"(saddr), "l"(g));
}
__device__ __forceinline__ void cp_commit() { asm volatile("cp.async.commit_group;"); }
__device__ __forceinline__ void cp_wait1() {
    asm volatile("cp.async.wait_group 1;" ::: "memory");
}
__device__ __forceinline__ void named_bar(int id) {
    asm volatile("bar.sync %0, 128;" :: "r"(id) : "memory");
}
__device__ __forceinline__ void ldm4(uint32_t d[4], uint32_t a) {
    asm volatile("ldmatrix.sync.aligned.m8n8.x4.shared.b16 {%0,%1,%2,%3}, [%4];"
        : "=r"(d[0]), "=r"(d[1]), "=r"(d[2]), "=r"(d[3]) : "r"(a));
}
__device__ __forceinline__ void ldm4t(uint32_t d[4], uint32_t a) {
    asm volatile("ldmatrix.sync.aligned.m8n8.x4.trans.shared.b16 {%0,%1,%2,%3}, [%4];"
        : "=r"(d[0]), "=r"(d[1]), "=r"(d[2]), "=r"(d[3]) : "r"(a));
}
__device__ __forceinline__ void mma16816(float c[4], const uint32_t a[4],
                                         uint32_t b0, uint32_t b1) {
    asm volatile("mma.sync.aligned.m16n8k16.row.col.f32.bf16.bf16.f32 "
        "{%0,%1,%2,%3}, {%4,%5,%6,%7}, {%8,%9}, {%0,%1,%2,%3};"
        : "+f"(c[0]), "+f"(c[1]), "+f"(c[2]), "+f"(c[3])
        : "r"(a[0]), "r"(a[1]), "r"(a[2]), "r"(a[3]), "r"(b0), "r"(b1));
}
__device__ __forceinline__ uint32_t pack_bf2(float a, float b) {
    __nv_bfloat162 t = __floats2bfloat162_rn(a, b);
    return *reinterpret_cast<uint32_t*>(&t);
}
__device__ __forceinline__ float bhi(float x) {
    return __bfloat162float(__float2bfloat16(x));
}

// ============================================================================
// prep: fp32 weights -> hi/lo bf16, K-padded, chunk-sequential [k16][264] planes
// ============================================================================
struct PrepP { const float* w[10]; };   // pw0..7, feature_w, views_w

__global__ void prep_kernel(PrepP pp) {
    const int cum[11] = {0,6,22,38,54,70,92,108,124,140,160};
    for (unsigned e = blockIdx.x * blockDim.x + threadIdx.x; e < 675840u;
         e += gridDim.x * blockDim.x) {
        unsigned g = e / 4224u, rem = e - g * 4224u;
        unsigned r = rem / 264u, c = rem - r * 264u;
        int l = 9;
        for (int i = 1; i <= 9; i++) { if ((int)g < cum[i]) { l = i - 1; break; } }
        int krow = (int)(g - cum[l]) * 16 + (int)r;
        int N = (l == 9) ? 128 : 256;
        int sr = krow;
        if (l == 0)      sr = (krow < 84)  ? krow : -1;
        else if (l == 5) sr = (krow < 84)  ? krow : (krow < 96 ? -1 : krow - 12);
        else if (l == 9) sr = (krow < 310) ? krow : -1;
        float v = 0.f;
        if (sr >= 0 && (int)c < N) v = pp.w[l][(size_t)sr * N + c];
        __nv_bfloat16 hb = __float2bfloat16(v);
        __nv_bfloat16 lb = __float2bfloat16(v - __bfloat162float(hb));
        char* p = (char*)g_wbuf + (size_t)g * CHB + r * WSTRG + c * 2u;
        *(__nv_bfloat16*)p = hb;
        *(__nv_bfloat16*)(p + WLO) = lb;
    }
}

// ============================================================================
// per-group slice loader: chunk g's wn-strip -> slice buffer b
// ============================================================================
template<int N8>
__device__ __forceinline__ void load_slice(uint32_t base32, int wn, int lane,
                                           int g, int b) {
    const char* gsrc = (const char*)g_wbuf + (size_t)g * CHB
                     + (unsigned)wn * (N8 == 8 ? 128u : 64u);
    uint32_t dst = base32 + SLB + (unsigned)wn * GRPSTR + (unsigned)b * BUFSTR;
    if (N8 == 8) {
        #pragma unroll
        for (int j = 0; j < 8; j++) {
            unsigned idx = (unsigned)lane + j * 32u;       // 0..255
            unsigned r = idx >> 4, rem = idx & 15u;
            unsigned pl = rem >> 3, c16 = (rem & 7u) * 16u;
            cp_async16(dst + pl * SLO + r * SSTR + c16,
                       gsrc + pl * WLO + r * WSTRG + c16);
        }
    } else {
        #pragma unroll
        for (int j = 0; j < 4; j++) {
            unsigned idx = (unsigned)lane + j * 32u;       // 0..127
            unsigned r = idx >> 3, rem = idx & 7u;
            unsigned pl = rem >> 2, c16 = (rem & 3u) * 16u;
            cp_async16(dst + pl * SLO + r * SSTR + c16,
                       gsrc + pl * WLO + r * WSTRG + c16);
        }
    }
}

// ============================================================================
// chunk compute: acc += A[128, k16] * Wslice[k16, 64|32]   (3-term split)
// ============================================================================
template<int N8>
__device__ __forceinline__ void chunk_mma(uint32_t base32, uint32_t wslice,
                                          int wm, int lane,
                                          int kcol, float acc[2][8][4]) {
    const uint32_t arow = (uint32_t)(wm * 32 + (lane & 15));
    const uint32_t acol = (uint32_t)kcol + (uint32_t)((lane >> 4) << 3);
    uint32_t a0 = base32 + A_HI + arow * ASTR + acol * 2u;
    uint32_t a1 = a0 + 16u * ASTR;
    uint32_t ahi[2][4], alo[2][4], b[N8 / 2][4];
    ldm4(ahi[0], a0); ldm4(ahi[1], a1);
    ldm4(alo[0], a0 + A_LO); ldm4(alo[1], a1 + A_LO);
    uint32_t wb = wslice + (uint32_t)(lane & 15) * SSTR
                + (uint32_t)((lane >> 4) << 3) * 2u;
    #pragma unroll
    for (int g2 = 0; g2 < N8 / 2; g2++) ldm4t(b[g2], wb + g2 * 32u);
    #pragma unroll
    for (int mt = 0; mt < 2; mt++)
        #pragma unroll
        for (int n8 = 0; n8 < N8; n8++)
            mma16816(acc[mt][n8], ahi[mt], b[n8 >> 1][(n8 & 1) * 2], b[n8 >> 1][(n8 & 1) * 2 + 1]);
    #pragma unroll
    for (int mt = 0; mt < 2; mt++)
        #pragma unroll
        for (int n8 = 0; n8 < N8; n8++)
            mma16816(acc[mt][n8], alo[mt], b[n8 >> 1][(n8 & 1) * 2], b[n8 >> 1][(n8 & 1) * 2 + 1]);
    #pragma unroll
    for (int g2 = 0; g2 < N8 / 2; g2++) ldm4t(b[g2], wb + SLO + g2 * 32u);
    #pragma unroll
    for (int mt = 0; mt < 2; mt++)
        #pragma unroll
        for (int n8 = 0; n8 < N8; n8++)
            mma16816(acc[mt][n8], ahi[mt], b[n8 >> 1][(n8 & 1) * 2], b[n8 >> 1][(n8 & 1) * 2 + 1]);
}

// ============================================================================
struct MainP {
    const float *input_pts, *input_views, *input_pls;
    const float *bias[9];          // pb0..7, feature_b
    const float *views_b;
    const float *alpha_w, *alpha_b;
    const float *rgb_w, *rgb_b;
    float* out;
};

extern __shared__ char smdyn[];

__global__ void __launch_bounds__(NTH, 1) nerf_hmma(MainP P) {
    char* sm = smdyn;
    const uint32_t base32 = smem_u32(sm);
    const int tid = threadIdx.x, lane = tid & 31, wid = tid >> 5;
    const int wn = wid >> 2, wm = wid & 3;      // group=wn spans 4 SMSPs
    const bool loader = (wm == wn);             // diagonal: 1 loader per SMSP
    const int barid = 1 + wn;
    const int blk = blockIdx.x;

    // prologue: loaders prefetch chunk 0 slices
    if (loader) { load_slice<8>(base32, wn, lane, 0, 0); cp_commit(); }

    // e_pts build: cols 0..83, pad 84..95 zero
    if (tid < 128) {
        size_t gidx = (size_t)blk * 128 + tid;
        float4 p4 = *reinterpret_cast<const float4*>(P.input_pts + gidx * 4);
        float xs[4] = {p4.x, p4.y, p4.z, p4.w};
        float vals[96];
        #pragma unroll
        for (int d = 0; d < 4; d++) vals[d] = xs[d];
        #pragma unroll
        for (int d = 0; d < 4; d++) {
            float f = 1.f;
            #pragma unroll
            for (int l = 0; l < 10; l++) {
                float sn, cs; sincosf(xs[d] * f, &sn, &cs);
                vals[4 + d * 20 + l * 2]     = sn;
                vals[4 + d * 20 + l * 2 + 1] = cs;
                f *= 2.f;
            }
        }
        #pragma unroll
        for (int k = 84; k < 96; k++) vals[k] = 0.f;
        char* rh = sm + A_HI + (uint32_t)tid * ASTR;
        #pragma unroll 4
        for (int k = 0; k < 96; k += 2) {
            float f0 = vals[k], f1 = vals[k + 1];
            *(uint32_t*)(rh + k * 2)        = pack_bf2(f0, f1);
            *(uint32_t*)(rh + A_LO + k * 2) = pack_bf2(f0 - bhi(f0), f1 - bhi(f1));
        }
    }
    __syncthreads();

    const int L_koff[9] = {0, 96, 96, 96, 96, 0, 96, 96, 96};
    const int L_nch[9]  = {6, 16, 16, 16, 16, 22, 16, 16, 16};
    const uint32_t myslb = base32 + SLB + (uint32_t)wn * GRPSTR;
    float acc[2][8][4];
    int g = 0;

    #pragma unroll 1
    for (int l = 0; l < 9; l++) {
        #pragma unroll
        for (int mt = 0; mt < 2; mt++)
            #pragma unroll
            for (int n8 = 0; n8 < 8; n8++)
                #pragma unroll
                for (int q = 0; q < 4; q++) acc[mt][n8][q] = 0.f;

        const int koff = L_koff[l], nch = L_nch[l];
        #pragma unroll 1
        for (int ch = 0; ch < nch; ch++) {
            named_bar(barid);                    // group done with buf (g+1)&1
            if (loader) {
                if (g + 1 < NCHTOT) {
                    if (g + 1 >= 140) load_slice<4>(base32, wn, lane, g + 1, (g + 1) & 1);
                    else              load_slice<8>(base32, wn, lane, g + 1, (g + 1) & 1);
                }
                cp_commit();
                cp_wait1();                      // chunk g slice landed
            }
            named_bar(barid);                    // visible to group
            chunk_mma<8>(base32, myslb + (uint32_t)(g & 1) * BUFSTR,
                         wm, lane, koff + ch * 16, acc);
            g++;
        }
        __syncthreads();                         // all MMA reads of A done

        // ---- epilogue: bias (+relu) (+alpha) -> split -> A hi/lo -------------
        const bool relu = (l != 8);
        const uint32_t colbase = (l == 8) ? 0u : 96u;
        const float* bias = P.bias[l];
        float ap[2][2] = {{0.f, 0.f}, {0.f, 0.f}};
        #pragma unroll
        for (int mt = 0; mt < 2; mt++) {
            #pragma unroll
            for (int half = 0; half < 2; half++) {
                const uint32_t row = (uint32_t)(wm * 32 + mt * 16 + half * 8 + (lane >> 2));
                char* rh = sm + A_HI + row * ASTR + colbase * 2u;
                #pragma unroll
                for (int n8 = 0; n8 < 8; n8++) {
                    const int col = wn * 64 + n8 * 8 + (lane & 3) * 2;
                    float2 bv = *(const float2*)(bias + col);
                    float f0 = acc[mt][n8][half * 2]     + bv.x;
                    float f1 = acc[mt][n8][half * 2 + 1] + bv.y;
                    if (relu) { f0 = fmaxf(f0, 0.f); f1 = fmaxf(f1, 0.f); }
                    if (l == 7) {
                        float2 aw = *(const float2*)(P.alpha_w + col);
                        ap[mt][half] += f0 * aw.x + f1 * aw.y;
                    }
                    *(uint32_t*)(rh + col * 2)        = pack_bf2(f0, f1);
                    *(uint32_t*)(rh + A_LO + col * 2) = pack_bf2(f0 - bhi(f0), f1 - bhi(f1));
                }
            }
        }
        if (l == 7) {        // alpha partials -> A_HI row pad
            #pragma unroll
            for (int mt = 0; mt < 2; mt++)
                #pragma unroll
                for (int half = 0; half < 2; half++) {
                    float v = ap[mt][half];
                    v += __shfl_xor_sync(0xffffffffu, v, 1);
                    v += __shfl_xor_sync(0xffffffffu, v, 2);
                    if ((lane & 3) == 0) {
                        uint32_t row = (uint32_t)(wm * 32 + mt * 16 + half * 8 + (lane >> 2));
                        *(float*)(sm + A_HI + row * ASTR + APAD + wn * 4) = v;
                    }
                }
            __syncthreads();
            if (tid < 128) {
                char* rp = sm + A_HI + (uint32_t)tid * ASTR + APAD;
                float a = P.alpha_b[0];
                #pragma unroll
                for (int w = 0; w < 4; w++) a += *(float*)(rp + w * 4);
                P.out[(size_t)blk * 128 + tid] = a;
            }
        }
        if (l == 8 && tid < 128) {   // e_view into cols 256..319 (310..319 zero)
            size_t gidx = (size_t)blk * 128 + tid;
            float xs[6];
            xs[0] = P.input_views[gidx * 3];     xs[1] = P.input_views[gidx * 3 + 1];
            xs[2] = P.input_views[gidx * 3 + 2]; xs[3] = P.input_pls[gidx * 3];
            xs[4] = P.input_pls[gidx * 3 + 1];   xs[5] = P.input_pls[gidx * 3 + 2];
            float vals[64];
            #pragma unroll
            for (int d = 0; d < 6; d++) vals[d] = xs[d];
            #pragma unroll
            for (int d = 0; d < 6; d++) {
                float f = 1.f;
                #pragma unroll
                for (int q = 0; q < 4; q++) {
                    float sn, cs; sincosf(xs[d] * f, &sn, &cs);
                    vals[6 + d * 8 + q * 2]     = sn;
                    vals[6 + d * 8 + q * 2 + 1] = cs;
                    f *= 2.f;
                }
            }
            #pragma unroll
            for (int k = 54; k < 64; k++) vals[k] = 0.f;
            char* rh = sm + A_HI + (uint32_t)tid * ASTR + 256u * 2u;
            #pragma unroll 4
            for (int k = 0; k < 64; k += 2) {
                float f0 = vals[k], f1 = vals[k + 1];
                *(uint32_t*)(rh + k * 2)        = pack_bf2(f0, f1);
                *(uint32_t*)(rh + A_LO + k * 2) = pack_bf2(f0 - bhi(f0), f1 - bhi(f1));
            }
        }
        __syncthreads();                         // A rewrite visible to all
    }

    // ---- views layer: K=320, N=128 -------------------------------------------
    #pragma unroll
    for (int mt = 0; mt < 2; mt++)
        #pragma unroll
        for (int n8 = 0; n8 < 8; n8++)
            #pragma unroll
            for (int q = 0; q < 4; q++) acc[mt][n8][q] = 0.f;
    #pragma unroll 1
    for (int ch = 0; ch < 20; ch++) {
        named_bar(barid);
        if (loader) {
            if (g + 1 < NCHTOT) load_slice<4>(base32, wn, lane, g + 1, (g + 1) & 1);
            cp_commit();
            cp_wait1();
        }
        named_bar(barid);
        chunk_mma<4>(base32, myslb + (uint32_t)(g & 1) * BUFSTR, wm, lane, ch * 16, acc);
        g++;
    }
    __syncthreads();

    // ---- rgb head: relu(C + views_b) . rgb_w, fp32 ----------------------------
    float rp[2][2][3] = {};
    #pragma unroll
    for (int mt = 0; mt < 2; mt++)
        #pragma unroll
        for (int half = 0; half < 2; half++)
            #pragma unroll
            for (int n8 = 0; n8 < 4; n8++) {
                const int col = wn * 32 + n8 * 8 + (lane & 3) * 2;
                float f0 = fmaxf(acc[mt][n8][half * 2]     + P.views_b[col],     0.f);
                float f1 = fmaxf(acc[mt][n8][half * 2 + 1] + P.views_b[col + 1], 0.f);
                const float* w0 = P.rgb_w + (size_t)col * 3;
                #pragma unroll
                for (int k = 0; k < 3; k++)
                    rp[mt][half][k] += f0 * w0[k] + f1 * w0[3 + k];
            }
    #pragma unroll
    for (int mt = 0; mt < 2; mt++)
        #pragma unroll
        for (int half = 0; half < 2; half++) {
            #pragma unroll
            for (int k = 0; k < 3; k++) {
                float v = rp[mt][half][k];
                v += __shfl_xor_sync(0xffffffffu, v, 1);
                v += __shfl_xor_sync(0xffffffffu, v, 2);
                rp[mt][half][k] = v;
            }
            if ((lane & 3) == 0) {
                uint32_t row = (uint32_t)(wm * 32 + mt * 16 + half * 8 + (lane >> 2));
                char* p = sm + PRGB + (row * 4 + wn) * 12;
                #pragma unroll
                for (int k = 0; k < 3; k++) *(float*)(p + k * 4) = rp[mt][half][k];
            }
        }
    __syncthreads();
    if (tid < 128) {
        float r[3] = {P.rgb_b[0], P.rgb_b[1], P.rgb_b[2]};
        char* p = sm + PRGB + (uint32_t)tid * 48;
        #pragma unroll
        for (int w = 0; w < 4; w++)
            #pragma unroll
            for (int k = 0; k < 3; k++) r[k] += *(float*)(p + w * 12 + k * 4);
        size_t gidx = (size_t)blk * 128 + tid;
        #pragma unroll
        for (int k = 0; k < 3; k++) P.out[(size_t)NPTS + gidx * 3 + k] = r[k];
    }
}

// ============================================================================
extern "C" void kernel_launch(void* const* d_in, const int* in_sizes, int n_in,
                              void* d_out, int out_size)
{
    (void)in_sizes; (void)n_in; (void)out_size;

    PrepP pp;
    for (int i = 0; i < 8; i++) pp.w[i] = (const float*)d_in[3 + 2 * i];
    pp.w[8] = (const float*)d_in[21];     // feature_w
    pp.w[9] = (const float*)d_in[19];     // views_w

    MainP P;
    P.input_pts   = (const float*)d_in[0];
    P.input_views = (const float*)d_in[1];
    P.input_pls   = (const float*)d_in[2];
    for (int i = 0; i < 8; i++) P.bias[i] = (const float*)d_in[4 + 2 * i];
    P.bias[8]  = (const float*)d_in[22];  // feature_b
    P.views_b  = (const float*)d_in[20];
    P.alpha_w  = (const float*)d_in[23];
    P.alpha_b  = (const float*)d_in[24];
    P.rgb_w    = (const float*)d_in[25];
    P.rgb_b    = (const float*)d_in[26];
    P.out      = (float*)d_out;

    prep_kernel<<<1320, 512>>>(pp);

    cudaFuncSetAttribute(nerf_hmma, cudaFuncAttributeMaxDynamicSharedMemorySize, SMEM_REQ);
    nerf_hmma<<<NBLK, NTH, SMEM_REQ>>>(P);
}

// round 11
// speedup vs baseline: 6.7572x; 1.4208x over previous
#include <cuda_runtime.h>
#include <cuda_fp16.h>
#include <cstdint>
#include <math.h>

// ============================================================================
// NeRF fused MLP via mma.sync (HMMA f16), 2-term fp16 split:
//   x*w ~= xh*wh + xl*wh   (xh,xl = fp16 hi/residual of activation; wh = fp16(w))
// Per CTA: 128 rows, 512 threads (16 warps). wn = wid>>2 (N quarter / group),
// wm = wid&3 -> each group spans all 4 SMSPs. Each group double-buffers ITS
// 64-col W slice per 32-k-row chunk via its diagonal loader warp + named bars.
// A hi/lo fp16 planes in SMEM [128][360]: cols 0..83 e_pts (pad->95),
// 96..351 h -> skip concat free. 80 chunks total.
// Output: d_out[0..N) = alpha, d_out[N..4N) = rgb row-major [N,3].
// ============================================================================

#define NPTS  131072
#define NTH   512
#define NBLK  (NPTS / 128)
#define NCHTOT 80

// ---- smem byte offsets -------------------------------------------------------
#define A_HI   0u
#define A_LO   92160u
#define ASTR   720u          // 360 fp16 per row (704 data + 16 pad for alpha)
#define APAD   704u
#define SLB    184320u       // W slices: 4 groups x 2 bufs x 4608 B
#define GRPSTR 9216u
#define BUFSTR 4608u
#define SSTR   144u          // slice row stride (conflict-free ldmatrix)
#define PRGB   184320u       // rgb partials overlay slices (after full sync)
#define SMEM_REQ 221184
#define CHB    16896u        // bytes per weight chunk: 32 rows x 528 B
#define WSTRG  528u          // g_wbuf row stride (264 fp16)

__device__ __align__(16) __half g_wbuf[675840];   // 80 * 8448 halfs

// ---- helpers -------------------------------------------------------------------
__device__ __forceinline__ uint32_t smem_u32(const void* p) {
    uint32_t a;
    asm("{ .reg .u64 t; cvta.to.shared.u64 t, %1; cvt.u32.u64 %0, t; }"
        : "=r"(a) : "l"(p));
    return a;
}
__device__ __forceinline__ void cp_async16(uint32_t saddr, const void* g) {
    asm volatile("cp.async.cg.shared.global [%0], [%1], 16;" :: "r"(saddr), "l"(g));
}
__device__ __forceinline__ void cp_commit() { asm volatile("cp.async.commit_group;"); }
__device__ __forceinline__ void cp_wait1() {
    asm volatile("cp.async.wait_group 1;" ::: "memory");
}
__device__ __forceinline__ void named_bar(int id) {
    asm volatile("bar.sync %0, 128;" :: "r"(id) : "memory");
}
__device__ __forceinline__ void ldm4(uint32_t d[4], uint32_t a) {
    asm volatile("ldmatrix.sync.aligned.m8n8.x4.shared.b16 {%0,%1,%2,%3}, [%4];"
        : "=r"(d[0]), "=r"(d[1]), "=r"(d[2]), "=r"(d[3]) : "r"(a));
}
__device__ __forceinline__ void ldm4t(uint32_t d[4], uint32_t a) {
    asm volatile("ldmatrix.sync.aligned.m8n8.x4.trans.shared.b16 {%0,%1,%2,%3}, [%4];"
        : "=r"(d[0]), "=r"(d[1]), "=r"(d[2]), "=r"(d[3]) : "r"(a));
}
__device__ __forceinline__ void mma16816(float c[4], const uint32_t a[4],
                                         uint32_t b0, uint32_t b1) {
    asm volatile("mma.sync.aligned.m16n8k16.row.col.f32.f16.f16.f32 "
        "{%0,%1,%2,%3}, {%4,%5,%6,%7}, {%8,%9}, {%0,%1,%2,%3};"
        : "+f"(c[0]), "+f"(c[1]), "+f"(c[2]), "+f"(c[3])
        : "r"(a[0]), "r"(a[1]), "r"(a[2]), "r"(a[3]), "r"(b0), "r"(b1));
}
__device__ __forceinline__ uint32_t pack_h2(float a, float b) {
    __half2 t = __floats2half2_rn(a, b);
    return *reinterpret_cast<uint32_t*>(&t);
}
__device__ __forceinline__ float hhi(float x) {
    return __half2float(__float2half_rn(x));
}

// ============================================================================
// prep: fp32 weights -> fp16, K-padded, chunk-sequential [k32][264] planes
// chunk order: L0(3) L1..L4(8 ea) L5(11) L6(8) L7(8) feat(8) views(10) = 80
// ============================================================================
struct PrepP { const float* w[10]; };   // pw0..7, feature_w, views_w

__global__ void prep_kernel(PrepP pp) {
    const int cum[11] = {0,3,11,19,27,35,46,54,62,70,80};
    for (unsigned e = blockIdx.x * blockDim.x + threadIdx.x; e < 675840u;
         e += gridDim.x * blockDim.x) {
        unsigned g = e / 8448u, rem = e - g * 8448u;
        unsigned r = rem / 264u, c = rem - r * 264u;
        int l = 9;
        for (int i = 1; i <= 9; i++) { if ((int)g < cum[i]) { l = i - 1; break; } }
        int krow = (int)(g - cum[l]) * 32 + (int)r;
        int N = (l == 9) ? 128 : 256;
        int sr = krow;
        if (l == 0)      sr = (krow < 84)  ? krow : -1;
        else if (l == 5) sr = (krow < 84)  ? krow : (krow < 96 ? -1 : krow - 12);
        else if (l == 9) sr = (krow < 310) ? krow : -1;
        float v = 0.f;
        if (sr >= 0 && (int)c < N) v = pp.w[l][(size_t)sr * N + c];
        g_wbuf[(size_t)g * 8448u + r * 264u + c] = __float2half_rn(v);
    }
}

// ============================================================================
// per-group slice loader: chunk g's wn-strip (32 k-rows) -> slice buffer b
// ============================================================================
template<int N8>
__device__ __forceinline__ void load_slice(uint32_t base32, int wn, int lane,
                                           int g, int b) {
    const char* gsrc = (const char*)g_wbuf + (size_t)g * CHB
                     + (unsigned)wn * (N8 == 8 ? 128u : 64u);
    uint32_t dst = base32 + SLB + (unsigned)wn * GRPSTR + (unsigned)b * BUFSTR;
    if (N8 == 8) {        // 64 cols = 128 B/row, 32 rows -> 256 x 16B
        #pragma unroll
        for (int j = 0; j < 8; j++) {
            unsigned idx = (unsigned)lane + j * 32u;
            unsigned r = idx >> 3, c16 = (idx & 7u) * 16u;
            cp_async16(dst + r * SSTR + c16, gsrc + r * WSTRG + c16);
        }
    } else {              // 32 cols = 64 B/row -> 128 x 16B
        #pragma unroll
        for (int j = 0; j < 4; j++) {
            unsigned idx = (unsigned)lane + j * 32u;
            unsigned r = idx >> 2, c16 = (idx & 3u) * 16u;
            cp_async16(dst + r * SSTR + c16, gsrc + r * WSTRG + c16);
        }
    }
}

// ============================================================================
// chunk compute: acc += A[128, k32] * Wslice[k32, 64|32]   (2-term fp16)
// ============================================================================
template<int N8>
__device__ __forceinline__ void chunk_mma(uint32_t base32, uint32_t wslice,
                                          int wm, int lane,
                                          int kcol, float acc[2][8][4]) {
    #pragma unroll
    for (int ks = 0; ks < 2; ks++) {
        const uint32_t arow = (uint32_t)(wm * 32 + (lane & 15));
        const uint32_t acol = (uint32_t)(kcol + ks * 16) + (uint32_t)((lane >> 4) << 3);
        uint32_t a0 = base32 + A_HI + arow * ASTR + acol * 2u;
        uint32_t a1 = a0 + 16u * ASTR;
        uint32_t ahi[2][4], alo[2][4], b[N8 / 2][4];
        ldm4(ahi[0], a0); ldm4(ahi[1], a1);
        ldm4(alo[0], a0 + A_LO); ldm4(alo[1], a1 + A_LO);
        uint32_t wb = wslice + (uint32_t)(ks * 16 + (lane & 15)) * SSTR
                    + (uint32_t)((lane >> 4) << 3) * 2u;
        #pragma unroll
        for (int g2 = 0; g2 < N8 / 2; g2++) ldm4t(b[g2], wb + g2 * 32u);
        #pragma unroll
        for (int mt = 0; mt < 2; mt++)
            #pragma unroll
            for (int n8 = 0; n8 < N8; n8++)
                mma16816(acc[mt][n8], ahi[mt],
                         b[n8 >> 1][(n8 & 1) * 2], b[n8 >> 1][(n8 & 1) * 2 + 1]);
        #pragma unroll
        for (int mt = 0; mt < 2; mt++)
            #pragma unroll
            for (int n8 = 0; n8 < N8; n8++)
                mma16816(acc[mt][n8], alo[mt],
                         b[n8 >> 1][(n8 & 1) * 2], b[n8 >> 1][(n8 & 1) * 2 + 1]);
    }
}

// ============================================================================
struct MainP {
    const float *input_pts, *input_views, *input_pls;
    const float *bias[9];          // pb0..7, feature_b
    const float *views_b;
    const float *alpha_w, *alpha_b;
    const float *rgb_w, *rgb_b;
    float* out;
};

extern __shared__ char smdyn[];

__global__ void __launch_bounds__(NTH, 1) nerf_hmma(MainP P) {
    char* sm = smdyn;
    const uint32_t base32 = smem_u32(sm);
    const int tid = threadIdx.x, lane = tid & 31, wid = tid >> 5;
    const int wn = wid >> 2, wm = wid & 3;      // group=wn spans 4 SMSPs
    const bool loader = (wm == wn);             // diagonal: 1 loader per SMSP
    const int barid = 1 + wn;
    const int blk = blockIdx.x;

    // prologue: loaders prefetch chunk 0 slices
    if (loader) { load_slice<8>(base32, wn, lane, 0, 0); cp_commit(); }

    // e_pts build: cols 0..83, pad 84..95 zero
    if (tid < 128) {
        size_t gidx = (size_t)blk * 128 + tid;
        float4 p4 = *reinterpret_cast<const float4*>(P.input_pts + gidx * 4);
        float xs[4] = {p4.x, p4.y, p4.z, p4.w};
        float vals[96];
        #pragma unroll
        for (int d = 0; d < 4; d++) vals[d] = xs[d];
        #pragma unroll
        for (int d = 0; d < 4; d++) {
            float f = 1.f;
            #pragma unroll
            for (int l = 0; l < 10; l++) {
                float sn, cs; sincosf(xs[d] * f, &sn, &cs);
                vals[4 + d * 20 + l * 2]     = sn;
                vals[4 + d * 20 + l * 2 + 1] = cs;
                f *= 2.f;
            }
        }
        #pragma unroll
        for (int k = 84; k < 96; k++) vals[k] = 0.f;
        char* rh = sm + A_HI + (uint32_t)tid * ASTR;
        #pragma unroll 4
        for (int k = 0; k < 96; k += 2) {
            float f0 = vals[k], f1 = vals[k + 1];
            *(uint32_t*)(rh + k * 2)        = pack_h2(f0, f1);
            *(uint32_t*)(rh + A_LO + k * 2) = pack_h2(f0 - hhi(f0), f1 - hhi(f1));
        }
    }
    __syncthreads();

    const int L_koff[9] = {0, 96, 96, 96, 96, 0, 96, 96, 96};
    const int L_nch[9]  = {3, 8, 8, 8, 8, 11, 8, 8, 8};
    const uint32_t myslb = base32 + SLB + (uint32_t)wn * GRPSTR;
    float acc[2][8][4];
    int g = 0;

    #pragma unroll 1
    for (int l = 0; l < 9; l++) {
        #pragma unroll
        for (int mt = 0; mt < 2; mt++)
            #pragma unroll
            for (int n8 = 0; n8 < 8; n8++)
                #pragma unroll
                for (int q = 0; q < 4; q++) acc[mt][n8][q] = 0.f;

        const int koff = L_koff[l], nch = L_nch[l];
        #pragma unroll 1
        for (int ch = 0; ch < nch; ch++) {
            named_bar(barid);                    // group done with buf (g+1)&1
            if (loader) {
                if (g + 1 < NCHTOT) {
                    if (g + 1 >= 70) load_slice<4>(base32, wn, lane, g + 1, (g + 1) & 1);
                    else             load_slice<8>(base32, wn, lane, g + 1, (g + 1) & 1);
                }
                cp_commit();
                cp_wait1();                      // chunk g slice landed
            }
            named_bar(barid);                    // visible to group
            chunk_mma<8>(base32, myslb + (uint32_t)(g & 1) * BUFSTR,
                         wm, lane, koff + ch * 32, acc);
            g++;
        }
        __syncthreads();                         // all MMA reads of A done

        // ---- epilogue: bias (+relu) (+alpha) -> split -> A hi/lo -------------
        const bool relu = (l != 8);
        const uint32_t colbase = (l == 8) ? 0u : 96u;
        const float* bias = P.bias[l];
        float ap[2][2] = {{0.f, 0.f}, {0.f, 0.f}};
        #pragma unroll
        for (int mt = 0; mt < 2; mt++) {
            #pragma unroll
            for (int half = 0; half < 2; half++) {
                const uint32_t row = (uint32_t)(wm * 32 + mt * 16 + half * 8 + (lane >> 2));
                char* rh = sm + A_HI + row * ASTR + colbase * 2u;
                #pragma unroll
                for (int n8 = 0; n8 < 8; n8++) {
                    const int col = wn * 64 + n8 * 8 + (lane & 3) * 2;
                    float2 bv = *(const float2*)(bias + col);
                    float f0 = acc[mt][n8][half * 2]     + bv.x;
                    float f1 = acc[mt][n8][half * 2 + 1] + bv.y;
                    if (relu) { f0 = fmaxf(f0, 0.f); f1 = fmaxf(f1, 0.f); }
                    if (l == 7) {
                        float2 aw = *(const float2*)(P.alpha_w + col);
                        ap[mt][half] += f0 * aw.x + f1 * aw.y;
                    }
                    *(uint32_t*)(rh + col * 2)        = pack_h2(f0, f1);
                    *(uint32_t*)(rh + A_LO + col * 2) = pack_h2(f0 - hhi(f0), f1 - hhi(f1));
                }
            }
        }
        if (l == 7) {        // alpha partials -> A_HI row pad
            #pragma unroll
            for (int mt = 0; mt < 2; mt++)
                #pragma unroll
                for (int half = 0; half < 2; half++) {
                    float v = ap[mt][half];
                    v += __shfl_xor_sync(0xffffffffu, v, 1);
                    v += __shfl_xor_sync(0xffffffffu, v, 2);
                    if ((lane & 3) == 0) {
                        uint32_t row = (uint32_t)(wm * 32 + mt * 16 + half * 8 + (lane >> 2));
                        *(float*)(sm + A_HI + row * ASTR + APAD + wn * 4) = v;
                    }
                }
            __syncthreads();
            if (tid < 128) {
                char* rp = sm + A_HI + (uint32_t)tid * ASTR + APAD;
                float a = P.alpha_b[0];
                #pragma unroll
                for (int w = 0; w < 4; w++) a += *(float*)(rp + w * 4);
                P.out[(size_t)blk * 128 + tid] = a;
            }
        }
        if (l == 8 && tid < 128) {   // e_view into cols 256..319 (310..319 zero)
            size_t gidx = (size_t)blk * 128 + tid;
            float xs[6];
            xs[0] = P.input_views[gidx * 3];     xs[1] = P.input_views[gidx * 3 + 1];
            xs[2] = P.input_views[gidx * 3 + 2]; xs[3] = P.input_pls[gidx * 3];
            xs[4] = P.input_pls[gidx * 3 + 1];   xs[5] = P.input_pls[gidx * 3 + 2];
            float vals[64];
            #pragma unroll
            for (int d = 0; d < 6; d++) vals[d] = xs[d];
            #pragma unroll
            for (int d = 0; d < 6; d++) {
                float f = 1.f;
                #pragma unroll
                for (int q = 0; q < 4; q++) {
                    float sn, cs; sincosf(xs[d] * f, &sn, &cs);
                    vals[6 + d * 8 + q * 2]     = sn;
                    vals[6 + d * 8 + q * 2 + 1] = cs;
                    f *= 2.f;
                }
            }
            #pragma unroll
            for (int k = 54; k < 64; k++) vals[k] = 0.f;
            char* rh = sm + A_HI + (uint32_t)tid * ASTR + 256u * 2u;
            #pragma unroll 4
            for (int k = 0; k < 64; k += 2) {
                float f0 = vals[k], f1 = vals[k + 1];
                *(uint32_t*)(rh + k * 2)        = pack_h2(f0, f1);
                *(uint32_t*)(rh + A_LO + k * 2) = pack_h2(f0 - hhi(f0), f1 - hhi(f1));
            }
        }
        __syncthreads();                         // A rewrite visible to all
    }

    // ---- views layer: K=320, N=128 (10 chunks) --------------------------------
    #pragma unroll
    for (int mt = 0; mt < 2; mt++)
        #pragma unroll
        for (int n8 = 0; n8 < 8; n8++)
            #pragma unroll
            for (int q = 0; q < 4; q++) acc[mt][n8][q] = 0.f;
    #pragma unroll 1
    for (int ch = 0; ch < 10; ch++) {
        named_bar(barid);
        if (loader) {
            if (g + 1 < NCHTOT) load_slice<4>(base32, wn, lane, g + 1, (g + 1) & 1);
            cp_commit();
            cp_wait1();
        }
        named_bar(barid);
        chunk_mma<4>(base32, myslb + (uint32_t)(g & 1) * BUFSTR, wm, lane, ch * 32, acc);
        g++;
    }
    __syncthreads();

    // ---- rgb head: relu(C + views_b) . rgb_w, fp32 ----------------------------
    float rp[2][2][3] = {};
    #pragma unroll
    for (int mt = 0; mt < 2; mt++)
        #pragma unroll
        for (int half = 0; half < 2; half++)
            #pragma unroll
            for (int n8 = 0; n8 < 4; n8++) {
                const int col = wn * 32 + n8 * 8 + (lane & 3) * 2;
                float f0 = fmaxf(acc[mt][n8][half * 2]     + P.views_b[col],     0.f);
                float f1 = fmaxf(acc[mt][n8][half * 2 + 1] + P.views_b[col + 1], 0.f);
                const float* w0 = P.rgb_w + (size_t)col * 3;
                #pragma unroll
                for (int k = 0; k < 3; k++)
                    rp[mt][half][k] += f0 * w0[k] + f1 * w0[3 + k];
            }
    #pragma unroll
    for (int mt = 0; mt < 2; mt++)
        #pragma unroll
        for (int half = 0; half < 2; half++) {
            #pragma unroll
            for (int k = 0; k < 3; k++) {
                float v = rp[mt][half][k];
                v += __shfl_xor_sync(0xffffffffu, v, 1);
                v += __shfl_xor_sync(0xffffffffu, v, 2);
                rp[mt][half][k] = v;
            }
            if ((lane & 3) == 0) {
                uint32_t row = (uint32_t)(wm * 32 + mt * 16 + half * 8 + (lane >> 2));
                char* p = sm + PRGB + (row * 4 + wn) * 12;
                #pragma unroll
                for (int k = 0; k < 3; k++) *(float*)(p + k * 4) = rp[mt][half][k];
            }
        }
    __syncthreads();
    if (tid < 128) {
        float r[3] = {P.rgb_b[0], P.rgb_b[1], P.rgb_b[2]};
        char* p = sm + PRGB + (uint32_t)tid * 48;
        #pragma unroll
        for (int w = 0; w < 4; w++)
            #pragma unroll
            for (int k = 0; k < 3; k++) r[k] += *(float*)(p + w * 12 + k * 4);
        size_t gidx = (size_t)blk * 128 + tid;
        #pragma unroll
        for (int k = 0; k < 3; k++) P.out[(size_t)NPTS + gidx * 3 + k] = r[k];
    }
}

// ============================================================================
extern "C" void kernel_launch(void* const* d_in, const int* in_sizes, int n_in,
                              void* d_out, int out_size)
{
    (void)in_sizes; (void)n_in; (void)out_size;

    PrepP pp;
    for (int i = 0; i < 8; i++) pp.w[i] = (const float*)d_in[3 + 2 * i];
    pp.w[8] = (const float*)d_in[21];     // feature_w
    pp.w[9] = (const float*)d_in[19];     // views_w

    MainP P;
    P.input_pts   = (const float*)d_in[0];
    P.input_views = (const float*)d_in[1];
    P.input_pls   = (const float*)d_in[2];
    for (int i = 0; i < 8; i++) P.bias[i] = (const float*)d_in[4 + 2 * i];
    P.bias[8]  = (const float*)d_in[22];  // feature_b
    P.views_b  = (const float*)d_in[20];
    P.alpha_w  = (const float*)d_in[23];
    P.alpha_b  = (const float*)d_in[24];
    P.rgb_w    = (const float*)d_in[25];
    P.rgb_b    = (const float*)d_in[26];
    P.out      = (float*)d_out;

    prep_kernel<<<1320, 512>>>(pp);

    cudaFuncSetAttribute(nerf_hmma, cudaFuncAttributeMaxDynamicSharedMemorySize, SMEM_REQ);
    nerf_hmma<<<NBLK, NTH, SMEM_REQ>>>(P);
}

// round 12
// speedup vs baseline: 6.8268x; 1.0103x over previous
#include <cuda_runtime.h>
#include <cuda_fp16.h>
#include <cstdint>
#include <math.h>

// ============================================================================
// NeRF fused MLP via mma.sync (HMMA f16), 2-term fp16 split:
//   x*w ~= xh*wh + xl*wh
// Occupancy-2 version: CTA = 64 rows, 256 threads (8 warps), ~108 KB SMEM,
// 2 CTAs/SM so epilogues/barriers of one CTA overlap MMAs of the other.
//   wn = wid>>1 (N quarter / group, 2 warps), wm = wid&1 (row half).
// Per-group double-buffered 64-col W slices per 16-k-row chunk (loader =
// wm==0 warp) + named barriers. A hi/lo fp16 planes [64][360]:
//   cols 0..83 e_pts (pad->95), 96..351 h -> skip concat free.
// Output: d_out[0..N) = alpha, d_out[N..4N) = rgb row-major [N,3].
// ============================================================================

#define NPTS  131072
#define NTH   256
#define NBLK  (NPTS / 64)
#define NCHTOT 160

// ---- smem byte offsets -------------------------------------------------------
#define A_HI   0u
#define A_LO   46080u
#define ASTR   720u          // 360 fp16 per row (704 data + 16 pad for alpha)
#define APAD   704u
#define SLB    92160u        // W slices: 4 groups x 2 bufs x 2304 B
#define GRPSTR 4608u
#define BUFSTR 2304u
#define SSTR   144u          // slice row stride (conflict-free ldmatrix)
#define PRGB   92160u        // rgb partials overlay slices (after full sync)
#define SMEM_REQ 110592
#define CHB    8448u         // bytes per weight chunk: 16 rows x 528 B
#define WSTRG  528u          // g_wbuf row stride (264 fp16)

__device__ __align__(16) __half g_wbuf[675840];   // 160 * 4224 halfs

// ---- helpers -------------------------------------------------------------------
__device__ __forceinline__ uint32_t smem_u32(const void* p) {
    uint32_t a;
    asm("{ .reg .u64 t; cvta.to.shared.u64 t, %1; cvt.u32.u64 %0, t; }"
        : "=r"(a) : "l"(p));
    return a;
}
__device__ __forceinline__ void cp_async16(uint32_t saddr, const void* g) {
    asm volatile("cp.async.cg.shared.global [%0], [%1], 16;" :: "r"(saddr), "l"(g));
}
__device__ __forceinline__ void cp_commit() { asm volatile("cp.async.commit_group;"); }
__device__ __forceinline__ void cp_wait1() {
    asm volatile("cp.async.wait_group 1;" ::: "memory");
}
__device__ __forceinline__ void named_bar(int id) {
    asm volatile("bar.sync %0, 64;" :: "r"(id) : "memory");
}
__device__ __forceinline__ void ldm4(uint32_t d[4], uint32_t a) {
    asm volatile("ldmatrix.sync.aligned.m8n8.x4.shared.b16 {%0,%1,%2,%3}, [%4];"
        : "=r"(d[0]), "=r"(d[1]), "=r"(d[2]), "=r"(d[3]) : "r"(a));
}
__device__ __forceinline__ void ldm4t(uint32_t d[4], uint32_t a) {
    asm volatile("ldmatrix.sync.aligned.m8n8.x4.trans.shared.b16 {%0,%1,%2,%3}, [%4];"
        : "=r"(d[0]), "=r"(d[1]), "=r"(d[2]), "=r"(d[3]) : "r"(a));
}
__device__ __forceinline__ void mma16816(float c[4], const uint32_t a[4],
                                         uint32_t b0, uint32_t b1) {
    asm volatile("mma.sync.aligned.m16n8k16.row.col.f32.f16.f16.f32 "
        "{%0,%1,%2,%3}, {%4,%5,%6,%7}, {%8,%9}, {%0,%1,%2,%3};"
        : "+f"(c[0]), "+f"(c[1]), "+f"(c[2]), "+f"(c[3])
        : "r"(a[0]), "r"(a[1]), "r"(a[2]), "r"(a[3]), "r"(b0), "r"(b1));
}
__device__ __forceinline__ uint32_t pack_h2(float a, float b) {
    __half2 t = __floats2half2_rn(a, b);
    return *reinterpret_cast<uint32_t*>(&t);
}
__device__ __forceinline__ float hhi(float x) {
    return __half2float(__float2half_rn(x));
}

// ============================================================================
// prep: fp32 weights -> fp16, K-padded, chunk-sequential [k16][264] planes
// chunk order: L0(6) L1..L4(16 ea) L5(22) L6(16) L7(16) feat(16) views(20)=160
// ============================================================================
struct PrepP { const float* w[10]; };   // pw0..7, feature_w, views_w

__global__ void prep_kernel(PrepP pp) {
    const int cum[11] = {0,6,22,38,54,70,92,108,124,140,160};
    for (unsigned e = blockIdx.x * blockDim.x + threadIdx.x; e < 675840u;
         e += gridDim.x * blockDim.x) {
        unsigned g = e / 4224u, rem = e - g * 4224u;
        unsigned r = rem / 264u, c = rem - r * 264u;
        int l = 9;
        for (int i = 1; i <= 9; i++) { if ((int)g < cum[i]) { l = i - 1; break; } }
        int krow = (int)(g - cum[l]) * 16 + (int)r;
        int N = (l == 9) ? 128 : 256;
        int sr = krow;
        if (l == 0)      sr = (krow < 84)  ? krow : -1;
        else if (l == 5) sr = (krow < 84)  ? krow : (krow < 96 ? -1 : krow - 12);
        else if (l == 9) sr = (krow < 310) ? krow : -1;
        float v = 0.f;
        if (sr >= 0 && (int)c < N) v = pp.w[l][(size_t)sr * N + c];
        g_wbuf[(size_t)g * 4224u + r * 264u + c] = __float2half_rn(v);
    }
}

// ============================================================================
// per-group slice loader: chunk g's wn-strip (16 k-rows) -> slice buffer b
// ============================================================================
template<int N8>
__device__ __forceinline__ void load_slice(uint32_t base32, int wn, int lane,
                                           int g, int b) {
    const char* gsrc = (const char*)g_wbuf + (size_t)g * CHB
                     + (unsigned)wn * (N8 == 8 ? 128u : 64u);
    uint32_t dst = base32 + SLB + (unsigned)wn * GRPSTR + (unsigned)b * BUFSTR;
    if (N8 == 8) {        // 64 cols = 128 B/row, 16 rows -> 128 x 16B
        #pragma unroll
        for (int j = 0; j < 4; j++) {
            unsigned idx = (unsigned)lane + j * 32u;
            unsigned r = idx >> 3, c16 = (idx & 7u) * 16u;
            cp_async16(dst + r * SSTR + c16, gsrc + r * WSTRG + c16);
        }
    } else {              // 32 cols = 64 B/row -> 64 x 16B
        #pragma unroll
        for (int j = 0; j < 2; j++) {
            unsigned idx = (unsigned)lane + j * 32u;
            unsigned r = idx >> 2, c16 = (idx & 3u) * 16u;
            cp_async16(dst + r * SSTR + c16, gsrc + r * WSTRG + c16);
        }
    }
}

// ============================================================================
// chunk compute: acc += A[64, k16] * Wslice[k16, 64|32]   (2-term fp16)
// ============================================================================
template<int N8>
__device__ __forceinline__ void chunk_mma(uint32_t base32, uint32_t wslice,
                                          int wm, int lane,
                                          int kcol, float acc[2][8][4]) {
    const uint32_t arow = (uint32_t)(wm * 32 + (lane & 15));
    const uint32_t acol = (uint32_t)kcol + (uint32_t)((lane >> 4) << 3);
    uint32_t a0 = base32 + A_HI + arow * ASTR + acol * 2u;
    uint32_t a1 = a0 + 16u * ASTR;
    uint32_t ahi[2][4], alo[2][4], b[N8 / 2][4];
    ldm4(ahi[0], a0); ldm4(ahi[1], a1);
    ldm4(alo[0], a0 + A_LO); ldm4(alo[1], a1 + A_LO);
    uint32_t wb = wslice + (uint32_t)(lane & 15) * SSTR
                + (uint32_t)((lane >> 4) << 3) * 2u;
    #pragma unroll
    for (int g2 = 0; g2 < N8 / 2; g2++) ldm4t(b[g2], wb + g2 * 32u);
    #pragma unroll
    for (int mt = 0; mt < 2; mt++)
        #pragma unroll
        for (int n8 = 0; n8 < N8; n8++)
            mma16816(acc[mt][n8], ahi[mt],
                     b[n8 >> 1][(n8 & 1) * 2], b[n8 >> 1][(n8 & 1) * 2 + 1]);
    #pragma unroll
    for (int mt = 0; mt < 2; mt++)
        #pragma unroll
        for (int n8 = 0; n8 < N8; n8++)
            mma16816(acc[mt][n8], alo[mt],
                     b[n8 >> 1][(n8 & 1) * 2], b[n8 >> 1][(n8 & 1) * 2 + 1]);
}

// ============================================================================
struct MainP {
    const float *input_pts, *input_views, *input_pls;
    const float *bias[9];          // pb0..7, feature_b
    const float *views_b;
    const float *alpha_w, *alpha_b;
    const float *rgb_w, *rgb_b;
    float* out;
};

extern __shared__ char smdyn[];

__global__ void __launch_bounds__(NTH, 2) nerf_hmma(MainP P) {
    char* sm = smdyn;
    const uint32_t base32 = smem_u32(sm);
    const int tid = threadIdx.x, lane = tid & 31, wid = tid >> 5;
    const int wn = wid >> 1, wm = wid & 1;      // group=wn: warps 2wn, 2wn+1
    const bool loader = (wm == 0);
    const int barid = 1 + wn;
    const int blk = blockIdx.x;

    // prologue: loaders prefetch chunk 0 slices
    if (loader) { load_slice<8>(base32, wn, lane, 0, 0); cp_commit(); }

    // e_pts build: cols 0..83, pad 84..95 zero (64 rows)
    if (tid < 64) {
        size_t gidx = (size_t)blk * 64 + tid;
        float4 p4 = *reinterpret_cast<const float4*>(P.input_pts + gidx * 4);
        float xs[4] = {p4.x, p4.y, p4.z, p4.w};
        float vals[96];
        #pragma unroll
        for (int d = 0; d < 4; d++) vals[d] = xs[d];
        #pragma unroll
        for (int d = 0; d < 4; d++) {
            float f = 1.f;
            #pragma unroll
            for (int l = 0; l < 10; l++) {
                float sn, cs; sincosf(xs[d] * f, &sn, &cs);
                vals[4 + d * 20 + l * 2]     = sn;
                vals[4 + d * 20 + l * 2 + 1] = cs;
                f *= 2.f;
            }
        }
        #pragma unroll
        for (int k = 84; k < 96; k++) vals[k] = 0.f;
        char* rh = sm + A_HI + (uint32_t)tid * ASTR;
        #pragma unroll 4
        for (int k = 0; k < 96; k += 2) {
            float f0 = vals[k], f1 = vals[k + 1];
            *(uint32_t*)(rh + k * 2)        = pack_h2(f0, f1);
            *(uint32_t*)(rh + A_LO + k * 2) = pack_h2(f0 - hhi(f0), f1 - hhi(f1));
        }
    }
    __syncthreads();

    const int L_koff[9] = {0, 96, 96, 96, 96, 0, 96, 96, 96};
    const int L_nch[9]  = {6, 16, 16, 16, 16, 22, 16, 16, 16};
    const uint32_t myslb = base32 + SLB + (uint32_t)wn * GRPSTR;
    float acc[2][8][4];
    int g = 0;

    #pragma unroll 1
    for (int l = 0; l < 9; l++) {
        #pragma unroll
        for (int mt = 0; mt < 2; mt++)
            #pragma unroll
            for (int n8 = 0; n8 < 8; n8++)
                #pragma unroll
                for (int q = 0; q < 4; q++) acc[mt][n8][q] = 0.f;

        const int koff = L_koff[l], nch = L_nch[l];
        #pragma unroll 1
        for (int ch = 0; ch < nch; ch++) {
            named_bar(barid);                    // group done with buf (g+1)&1
            if (loader) {
                if (g + 1 < NCHTOT) {
                    if (g + 1 >= 140) load_slice<4>(base32, wn, lane, g + 1, (g + 1) & 1);
                    else              load_slice<8>(base32, wn, lane, g + 1, (g + 1) & 1);
                }
                cp_commit();
                cp_wait1();                      // chunk g slice landed
            }
            named_bar(barid);                    // visible to group
            chunk_mma<8>(base32, myslb + (uint32_t)(g & 1) * BUFSTR,
                         wm, lane, koff + ch * 16, acc);
            g++;
        }
        __syncthreads();                         // all MMA reads of A done

        // ---- epilogue: bias (+relu) (+alpha) -> split -> A hi/lo -------------
        const bool relu = (l != 8);
        const uint32_t colbase = (l == 8) ? 0u : 96u;
        const float* bias = P.bias[l];
        float ap[2][2] = {{0.f, 0.f}, {0.f, 0.f}};
        #pragma unroll
        for (int mt = 0; mt < 2; mt++) {
            #pragma unroll
            for (int half = 0; half < 2; half++) {
                const uint32_t row = (uint32_t)(wm * 32 + mt * 16 + half * 8 + (lane >> 2));
                char* rh = sm + A_HI + row * ASTR + colbase * 2u;
                #pragma unroll
                for (int n8 = 0; n8 < 8; n8++) {
                    const int col = wn * 64 + n8 * 8 + (lane & 3) * 2;
                    float2 bv = *(const float2*)(bias + col);
                    float f0 = acc[mt][n8][half * 2]     + bv.x;
                    float f1 = acc[mt][n8][half * 2 + 1] + bv.y;
                    if (relu) { f0 = fmaxf(f0, 0.f); f1 = fmaxf(f1, 0.f); }
                    if (l == 7) {
                        float2 aw = *(const float2*)(P.alpha_w + col);
                        ap[mt][half] += f0 * aw.x + f1 * aw.y;
                    }
                    *(uint32_t*)(rh + col * 2)        = pack_h2(f0, f1);
                    *(uint32_t*)(rh + A_LO + col * 2) = pack_h2(f0 - hhi(f0), f1 - hhi(f1));
                }
            }
        }
        if (l == 7) {        // alpha partials -> A_HI row pad
            #pragma unroll
            for (int mt = 0; mt < 2; mt++)
                #pragma unroll
                for (int half = 0; half < 2; half++) {
                    float v = ap[mt][half];
                    v += __shfl_xor_sync(0xffffffffu, v, 1);
                    v += __shfl_xor_sync(0xffffffffu, v, 2);
                    if ((lane & 3) == 0) {
                        uint32_t row = (uint32_t)(wm * 32 + mt * 16 + half * 8 + (lane >> 2));
                        *(float*)(sm + A_HI + row * ASTR + APAD + wn * 4) = v;
                    }
                }
            __syncthreads();
            if (tid < 64) {
                char* rp = sm + A_HI + (uint32_t)tid * ASTR + APAD;
                float a = P.alpha_b[0];
                #pragma unroll
                for (int w = 0; w < 4; w++) a += *(float*)(rp + w * 4);
                P.out[(size_t)blk * 64 + tid] = a;
            }
        }
        if (l == 8 && tid < 64) {    // e_view into cols 256..319 (310..319 zero)
            size_t gidx = (size_t)blk * 64 + tid;
            float xs[6];
            xs[0] = P.input_views[gidx * 3];     xs[1] = P.input_views[gidx * 3 + 1];
            xs[2] = P.input_views[gidx * 3 + 2]; xs[3] = P.input_pls[gidx * 3];
            xs[4] = P.input_pls[gidx * 3 + 1];   xs[5] = P.input_pls[gidx * 3 + 2];
            float vals[64];
            #pragma unroll
            for (int d = 0; d < 6; d++) vals[d] = xs[d];
            #pragma unroll
            for (int d = 0; d < 6; d++) {
                float f = 1.f;
                #pragma unroll
                for (int q = 0; q < 4; q++) {
                    float sn, cs; sincosf(xs[d] * f, &sn, &cs);
                    vals[6 + d * 8 + q * 2]     = sn;
                    vals[6 + d * 8 + q * 2 + 1] = cs;
                    f *= 2.f;
                }
            }
            #pragma unroll
            for (int k = 54; k < 64; k++) vals[k] = 0.f;
            char* rh = sm + A_HI + (uint32_t)tid * ASTR + 256u * 2u;
            #pragma unroll 4
            for (int k = 0; k < 64; k += 2) {
                float f0 = vals[k], f1 = vals[k + 1];
                *(uint32_t*)(rh + k * 2)        = pack_h2(f0, f1);
                *(uint32_t*)(rh + A_LO + k * 2) = pack_h2(f0 - hhi(f0), f1 - hhi(f1));
            }
        }
        __syncthreads();                         // A rewrite visible to all
    }

    // ---- views layer: K=320, N=128 (20 chunks) --------------------------------
    #pragma unroll
    for (int mt = 0; mt < 2; mt++)
        #pragma unroll
        for (int n8 = 0; n8 < 8; n8++)
            #pragma unroll
            for (int q = 0; q < 4; q++) acc[mt][n8][q] = 0.f;
    #pragma unroll 1
    for (int ch = 0; ch < 20; ch++) {
        named_bar(barid);
        if (loader) {
            if (g + 1 < NCHTOT) load_slice<4>(base32, wn, lane, g + 1, (g + 1) & 1);
            cp_commit();
            cp_wait1();
        }
        named_bar(barid);
        chunk_mma<4>(base32, myslb + (uint32_t)(g & 1) * BUFSTR, wm, lane, ch * 16, acc);
        g++;
    }
    __syncthreads();

    // ---- rgb head: relu(C + views_b) . rgb_w, fp32 ----------------------------
    float rp[2][2][3] = {};
    #pragma unroll
    for (int mt = 0; mt < 2; mt++)
        #pragma unroll
        for (int half = 0; half < 2; half++)
            #pragma unroll
            for (int n8 = 0; n8 < 4; n8++) {
                const int col = wn * 32 + n8 * 8 + (lane & 3) * 2;
                float f0 = fmaxf(acc[mt][n8][half * 2]     + P.views_b[col],     0.f);
                float f1 = fmaxf(acc[mt][n8][half * 2 + 1] + P.views_b[col + 1], 0.f);
                const float* w0 = P.rgb_w + (size_t)col * 3;
                #pragma unroll
                for (int k = 0; k < 3; k++)
                    rp[mt][half][k] += f0 * w0[k] + f1 * w0[3 + k];
            }
    #pragma unroll
    for (int mt = 0; mt < 2; mt++)
        #pragma unroll
        for (int half = 0; half < 2; half++) {
            #pragma unroll
            for (int k = 0; k < 3; k++) {
                float v = rp[mt][half][k];
                v += __shfl_xor_sync(0xffffffffu, v, 1);
                v += __shfl_xor_sync(0xffffffffu, v, 2);
                rp[mt][half][k] = v;
            }
            if ((lane & 3) == 0) {
                uint32_t row = (uint32_t)(wm * 32 + mt * 16 + half * 8 + (lane >> 2));
                char* p = sm + PRGB + (row * 4 + wn) * 12;
                #pragma unroll
                for (int k = 0; k < 3; k++) *(float*)(p + k * 4) = rp[mt][half][k];
            }
        }
    __syncthreads();
    if (tid < 64) {
        float r[3] = {P.rgb_b[0], P.rgb_b[1], P.rgb_b[2]};
        char* p = sm + PRGB + (uint32_t)tid * 48;
        #pragma unroll
        for (int w = 0; w < 4; w++)
            #pragma unroll
            for (int k = 0; k < 3; k++) r[k] += *(float*)(p + w * 12 + k * 4);
        size_t gidx = (size_t)blk * 64 + tid;
        #pragma unroll
        for (int k = 0; k < 3; k++) P.out[(size_t)NPTS + gidx * 3 + k] = r[k];
    }
}

// ============================================================================
extern "C" void kernel_launch(void* const* d_in, const int* in_sizes, int n_in,
                              void* d_out, int out_size)
{
    (void)in_sizes; (void)n_in; (void)out_size;

    PrepP pp;
    for (int i = 0; i < 8; i++) pp.w[i] = (const float*)d_in[3 + 2 * i];
    pp.w[8] = (const float*)d_in[21];     // feature_w
    pp.w[9] = (const float*)d_in[19];     // views_w

    MainP P;
    P.input_pts   = (const float*)d_in[0];
    P.input_views = (const float*)d_in[1];
    P.input_pls   = (const float*)d_in[2];
    for (int i = 0; i < 8; i++) P.bias[i] = (const float*)d_in[4 + 2 * i];
    P.bias[8]  = (const float*)d_in[22];  // feature_b
    P.views_b  = (const float*)d_in[20];
    P.alpha_w  = (const float*)d_in[23];
    P.alpha_b  = (const float*)d_in[24];
    P.rgb_w    = (const float*)d_in[25];
    P.rgb_b    = (const float*)d_in[26];
    P.out      = (float*)d_out;

    prep_kernel<<<1320, 512>>>(pp);

    cudaFuncSetAttribute(nerf_hmma, cudaFuncAttributeMaxDynamicSharedMemorySize, SMEM_REQ);
    nerf_hmma<<<NBLK, NTH, SMEM_REQ>>>(P);
}

// round 13
// speedup vs baseline: 11.7155x; 1.7161x over previous
#include <cuda_runtime.h>
#include <cuda_fp16.h>
#include <cstdint>
#include <math.h>

// ============================================================================
// NeRF fused MLP via mma.sync (HMMA f16), single-term fp16:
//   x*w ~= fp16(x)*fp16(w), fp32 accum.
// CTA = 64 rows, 256 threads (8 warps), ~83 KB SMEM, 2 CTAs/SM.
//   wn = wid>>1 (N quarter / group, 2 warps), wm = wid&1 (row half).
// Per-group double-buffered 64-col W slices per 32-k-row chunk (loader =
// wm==0 warp) + named barriers. A fp16 plane [64][360]:
//   cols 0..83 e_pts (pad->95), 96..351 h -> skip concat free.
// Output: d_out[0..N) = alpha, d_out[N..4N) = rgb row-major [N,3].
// ============================================================================

#define NPTS  131072
#define NTH   256
#define NBLK  (NPTS / 64)
#define NCHTOT 80

// ---- smem byte offsets -------------------------------------------------------
#define A_HI   0u
#define ASTR   720u          // 360 fp16 per row (704 data + 16 pad for alpha)
#define APAD   704u
#define SLB    46080u        // W slices: 4 groups x 2 bufs x 4608 B
#define GRPSTR 9216u
#define BUFSTR 4608u
#define SSTR   144u          // slice row stride (conflict-free ldmatrix)
#define PRGB   46080u        // rgb partials overlay slices (after full sync)
#define SMEM_REQ 82944
#define CHB    16896u        // bytes per weight chunk: 32 rows x 528 B
#define WSTRG  528u          // g_wbuf row stride (264 fp16)

__device__ __align__(16) __half g_wbuf[675840];   // 80 * 8448 halfs

// ---- helpers -------------------------------------------------------------------
__device__ __forceinline__ uint32_t smem_u32(const void* p) {
    uint32_t a;
    asm("{ .reg .u64 t; cvta.to.shared.u64 t, %1; cvt.u32.u64 %0, t; }"
        : "=r"(a) : "l"(p));
    return a;
}
__device__ __forceinline__ void cp_async16(uint32_t saddr, const void* g) {
    asm volatile("cp.async.cg.shared.global [%0], [%1], 16;" :: "r"(saddr), "l"(g));
}
__device__ __forceinline__ void cp_commit() { asm volatile("cp.async.commit_group;"); }
__device__ __forceinline__ void cp_wait1() {
    asm volatile("cp.async.wait_group 1;" ::: "memory");
}
__device__ __forceinline__ void named_bar(int id) {
    asm volatile("bar.sync %0, 64;" :: "r"(id) : "memory");
}
__device__ __forceinline__ void ldm4(uint32_t d[4], uint32_t a) {
    asm volatile("ldmatrix.sync.aligned.m8n8.x4.shared.b16 {%0,%1,%2,%3}, [%4];"
        : "=r"(d[0]), "=r"(d[1]), "=r"(d[2]), "=r"(d[3]) : "r"(a));
}
__device__ __forceinline__ void ldm4t(uint32_t d[4], uint32_t a) {
    asm volatile("ldmatrix.sync.aligned.m8n8.x4.trans.shared.b16 {%0,%1,%2,%3}, [%4];"
        : "=r"(d[0]), "=r"(d[1]), "=r"(d[2]), "=r"(d[3]) : "r"(a));
}
__device__ __forceinline__ void mma16816(float c[4], const uint32_t a[4],
                                         uint32_t b0, uint32_t b1) {
    asm volatile("mma.sync.aligned.m16n8k16.row.col.f32.f16.f16.f32 "
        "{%0,%1,%2,%3}, {%4,%5,%6,%7}, {%8,%9}, {%0,%1,%2,%3};"
        : "+f"(c[0]), "+f"(c[1]), "+f"(c[2]), "+f"(c[3])
        : "r"(a[0]), "r"(a[1]), "r"(a[2]), "r"(a[3]), "r"(b0), "r"(b1));
}
__device__ __forceinline__ uint32_t pack_h2(float a, float b) {
    __half2 t = __floats2half2_rn(a, b);
    return *reinterpret_cast<uint32_t*>(&t);
}

// ============================================================================
// prep: fp32 weights -> fp16, K-padded, chunk-sequential [k32][264] planes
// chunk order: L0(3) L1..L4(8 ea) L5(11) L6(8) L7(8) feat(8) views(10) = 80
// ============================================================================
struct PrepP { const float* w[10]; };   // pw0..7, feature_w, views_w

__global__ void prep_kernel(PrepP pp) {
    const int cum[11] = {0,3,11,19,27,35,46,54,62,70,80};
    for (unsigned e = blockIdx.x * blockDim.x + threadIdx.x; e < 675840u;
         e += gridDim.x * blockDim.x) {
        unsigned g = e / 8448u, rem = e - g * 8448u;
        unsigned r = rem / 264u, c = rem - r * 264u;
        int l = 9;
        for (int i = 1; i <= 9; i++) { if ((int)g < cum[i]) { l = i - 1; break; } }
        int krow = (int)(g - cum[l]) * 32 + (int)r;
        int N = (l == 9) ? 128 : 256;
        int sr = krow;
        if (l == 0)      sr = (krow < 84)  ? krow : -1;
        else if (l == 5) sr = (krow < 84)  ? krow : (krow < 96 ? -1 : krow - 12);
        else if (l == 9) sr = (krow < 310) ? krow : -1;
        float v = 0.f;
        if (sr >= 0 && (int)c < N) v = pp.w[l][(size_t)sr * N + c];
        g_wbuf[(size_t)g * 8448u + r * 264u + c] = __float2half_rn(v);
    }
}

// ============================================================================
// per-group slice loader: chunk g's wn-strip (32 k-rows) -> slice buffer b
// ============================================================================
template<int N8>
__device__ __forceinline__ void load_slice(uint32_t base32, int wn, int lane,
                                           int g, int b) {
    const char* gsrc = (const char*)g_wbuf + (size_t)g * CHB
                     + (unsigned)wn * (N8 == 8 ? 128u : 64u);
    uint32_t dst = base32 + SLB + (unsigned)wn * GRPSTR + (unsigned)b * BUFSTR;
    if (N8 == 8) {        // 64 cols = 128 B/row, 32 rows -> 256 x 16B
        #pragma unroll
        for (int j = 0; j < 8; j++) {
            unsigned idx = (unsigned)lane + j * 32u;
            unsigned r = idx >> 3, c16 = (idx & 7u) * 16u;
            cp_async16(dst + r * SSTR + c16, gsrc + r * WSTRG + c16);
        }
    } else {              // 32 cols = 64 B/row -> 128 x 16B
        #pragma unroll
        for (int j = 0; j < 4; j++) {
            unsigned idx = (unsigned)lane + j * 32u;
            unsigned r = idx >> 2, c16 = (idx & 3u) * 16u;
            cp_async16(dst + r * SSTR + c16, gsrc + r * WSTRG + c16);
        }
    }
}

// ============================================================================
// chunk compute: acc += A[64, k32] * Wslice[k32, 64|32]   (single-term fp16)
// ============================================================================
template<int N8>
__device__ __forceinline__ void chunk_mma(uint32_t base32, uint32_t wslice,
                                          int wm, int lane,
                                          int kcol, float acc[2][8][4]) {
    #pragma unroll
    for (int ks = 0; ks < 2; ks++) {
        const uint32_t arow = (uint32_t)(wm * 32 + (lane & 15));
        const uint32_t acol = (uint32_t)(kcol + ks * 16) + (uint32_t)((lane >> 4) << 3);
        uint32_t a0 = base32 + A_HI + arow * ASTR + acol * 2u;
        uint32_t a1 = a0 + 16u * ASTR;
        uint32_t ah[2][4], b[N8 / 2][4];
        ldm4(ah[0], a0); ldm4(ah[1], a1);
        uint32_t wb = wslice + (uint32_t)(ks * 16 + (lane & 15)) * SSTR
                    + (uint32_t)((lane >> 4) << 3) * 2u;
        #pragma unroll
        for (int g2 = 0; g2 < N8 / 2; g2++) ldm4t(b[g2], wb + g2 * 32u);
        #pragma unroll
        for (int mt = 0; mt < 2; mt++)
            #pragma unroll
            for (int n8 = 0; n8 < N8; n8++)
                mma16816(acc[mt][n8], ah[mt],
                         b[n8 >> 1][(n8 & 1) * 2], b[n8 >> 1][(n8 & 1) * 2 + 1]);
    }
}

// ============================================================================
struct MainP {
    const float *input_pts, *input_views, *input_pls;
    const float *bias[9];          // pb0..7, feature_b
    const float *views_b;
    const float *alpha_w, *alpha_b;
    const float *rgb_w, *rgb_b;
    float* out;
};

extern __shared__ char smdyn[];

__global__ void __launch_bounds__(NTH, 2) nerf_hmma(MainP P) {
    char* sm = smdyn;
    const uint32_t base32 = smem_u32(sm);
    const int tid = threadIdx.x, lane = tid & 31, wid = tid >> 5;
    const int wn = wid >> 1, wm = wid & 1;      // group=wn: warps 2wn, 2wn+1
    const bool loader = (wm == 0);
    const int barid = 1 + wn;
    const int blk = blockIdx.x;

    // prologue: loaders prefetch chunk 0 slices
    if (loader) { load_slice<8>(base32, wn, lane, 0, 0); cp_commit(); }

    // e_pts build: cols 0..83, pad 84..95 zero (64 rows)
    if (tid < 64) {
        size_t gidx = (size_t)blk * 64 + tid;
        float4 p4 = *reinterpret_cast<const float4*>(P.input_pts + gidx * 4);
        float xs[4] = {p4.x, p4.y, p4.z, p4.w};
        float vals[96];
        #pragma unroll
        for (int d = 0; d < 4; d++) vals[d] = xs[d];
        #pragma unroll
        for (int d = 0; d < 4; d++) {
            float f = 1.f;
            #pragma unroll
            for (int l = 0; l < 10; l++) {
                float sn, cs; sincosf(xs[d] * f, &sn, &cs);
                vals[4 + d * 20 + l * 2]     = sn;
                vals[4 + d * 20 + l * 2 + 1] = cs;
                f *= 2.f;
            }
        }
        #pragma unroll
        for (int k = 84; k < 96; k++) vals[k] = 0.f;
        char* rh = sm + A_HI + (uint32_t)tid * ASTR;
        #pragma unroll 4
        for (int k = 0; k < 96; k += 2)
            *(uint32_t*)(rh + k * 2) = pack_h2(vals[k], vals[k + 1]);
    }
    __syncthreads();

    const int L_koff[9] = {0, 96, 96, 96, 96, 0, 96, 96, 96};
    const int L_nch[9]  = {3, 8, 8, 8, 8, 11, 8, 8, 8};
    const uint32_t myslb = base32 + SLB + (uint32_t)wn * GRPSTR;
    float acc[2][8][4];
    int g = 0;

    #pragma unroll 1
    for (int l = 0; l < 9; l++) {
        #pragma unroll
        for (int mt = 0; mt < 2; mt++)
            #pragma unroll
            for (int n8 = 0; n8 < 8; n8++)
                #pragma unroll
                for (int q = 0; q < 4; q++) acc[mt][n8][q] = 0.f;

        const int koff = L_koff[l], nch = L_nch[l];
        #pragma unroll 1
        for (int ch = 0; ch < nch; ch++) {
            named_bar(barid);                    // group done with buf (g+1)&1
            if (loader) {
                if (g + 1 < NCHTOT) {
                    if (g + 1 >= 70) load_slice<4>(base32, wn, lane, g + 1, (g + 1) & 1);
                    else             load_slice<8>(base32, wn, lane, g + 1, (g + 1) & 1);
                }
                cp_commit();
                cp_wait1();                      // chunk g slice landed
            }
            named_bar(barid);                    // visible to group
            chunk_mma<8>(base32, myslb + (uint32_t)(g & 1) * BUFSTR,
                         wm, lane, koff + ch * 32, acc);
            g++;
        }
        __syncthreads();                         // all MMA reads of A done

        // ---- epilogue: bias (+relu) (+alpha) -> fp16 -> A plane --------------
        const bool relu = (l != 8);
        const uint32_t colbase = (l == 8) ? 0u : 96u;
        const float* bias = P.bias[l];
        float ap[2][2] = {{0.f, 0.f}, {0.f, 0.f}};
        #pragma unroll
        for (int mt = 0; mt < 2; mt++) {
            #pragma unroll
            for (int half = 0; half < 2; half++) {
                const uint32_t row = (uint32_t)(wm * 32 + mt * 16 + half * 8 + (lane >> 2));
                char* rh = sm + A_HI + row * ASTR + colbase * 2u;
                #pragma unroll
                for (int n8 = 0; n8 < 8; n8++) {
                    const int col = wn * 64 + n8 * 8 + (lane & 3) * 2;
                    float2 bv = *(const float2*)(bias + col);
                    float f0 = acc[mt][n8][half * 2]     + bv.x;
                    float f1 = acc[mt][n8][half * 2 + 1] + bv.y;
                    if (relu) { f0 = fmaxf(f0, 0.f); f1 = fmaxf(f1, 0.f); }
                    if (l == 7) {
                        float2 aw = *(const float2*)(P.alpha_w + col);
                        ap[mt][half] += f0 * aw.x + f1 * aw.y;
                    }
                    *(uint32_t*)(rh + col * 2) = pack_h2(f0, f1);
                }
            }
        }
        if (l == 7) {        // alpha partials -> A plane row pad
            #pragma unroll
            for (int mt = 0; mt < 2; mt++)
                #pragma unroll
                for (int half = 0; half < 2; half++) {
                    float v = ap[mt][half];
                    v += __shfl_xor_sync(0xffffffffu, v, 1);
                    v += __shfl_xor_sync(0xffffffffu, v, 2);
                    if ((lane & 3) == 0) {
                        uint32_t row = (uint32_t)(wm * 32 + mt * 16 + half * 8 + (lane >> 2));
                        *(float*)(sm + A_HI + row * ASTR + APAD + wn * 4) = v;
                    }
                }
            __syncthreads();
            if (tid < 64) {
                char* rp = sm + A_HI + (uint32_t)tid * ASTR + APAD;
                float a = P.alpha_b[0];
                #pragma unroll
                for (int w = 0; w < 4; w++) a += *(float*)(rp + w * 4);
                P.out[(size_t)blk * 64 + tid] = a;
            }
        }
        if (l == 8 && tid < 64) {    // e_view into cols 256..319 (310..319 zero)
            size_t gidx = (size_t)blk * 64 + tid;
            float xs[6];
            xs[0] = P.input_views[gidx * 3];     xs[1] = P.input_views[gidx * 3 + 1];
            xs[2] = P.input_views[gidx * 3 + 2]; xs[3] = P.input_pls[gidx * 3];
            xs[4] = P.input_pls[gidx * 3 + 1];   xs[5] = P.input_pls[gidx * 3 + 2];
            float vals[64];
            #pragma unroll
            for (int d = 0; d < 6; d++) vals[d] = xs[d];
            #pragma unroll
            for (int d = 0; d < 6; d++) {
                float f = 1.f;
                #pragma unroll
                for (int q = 0; q < 4; q++) {
                    float sn, cs; sincosf(xs[d] * f, &sn, &cs);
                    vals[6 + d * 8 + q * 2]     = sn;
                    vals[6 + d * 8 + q * 2 + 1] = cs;
                    f *= 2.f;
                }
            }
            #pragma unroll
            for (int k = 54; k < 64; k++) vals[k] = 0.f;
            char* rh = sm + A_HI + (uint32_t)tid * ASTR + 256u * 2u;
            #pragma unroll 4
            for (int k = 0; k < 64; k += 2)
                *(uint32_t*)(rh + k * 2) = pack_h2(vals[k], vals[k + 1]);
        }
        __syncthreads();                         // A rewrite visible to all
    }

    // ---- views layer: K=320, N=128 (10 chunks) --------------------------------
    #pragma unroll
    for (int mt = 0; mt < 2; mt++)
        #pragma unroll
        for (int n8 = 0; n8 < 8; n8++)
            #pragma unroll
            for (int q = 0; q < 4; q++) acc[mt][n8][q] = 0.f;
    #pragma unroll 1
    for (int ch = 0; ch < 10; ch++) {
        named_bar(barid);
        if (loader) {
            if (g + 1 < NCHTOT) load_slice<4>(base32, wn, lane, g + 1, (g + 1) & 1);
            cp_commit();
            cp_wait1();
        }
        named_bar(barid);
        chunk_mma<4>(base32, myslb + (uint32_t)(g & 1) * BUFSTR, wm, lane, ch * 32, acc);
        g++;
    }
    __syncthreads();

    // ---- rgb head: relu(C + views_b) . rgb_w, fp32 ----------------------------
    float rp[2][2][3] = {};
    #pragma unroll
    for (int mt = 0; mt < 2; mt++)
        #pragma unroll
        for (int half = 0; half < 2; half++)
            #pragma unroll
            for (int n8 = 0; n8 < 4; n8++) {
                const int col = wn * 32 + n8 * 8 + (lane & 3) * 2;
                float f0 = fmaxf(acc[mt][n8][half * 2]     + P.views_b[col],     0.f);
                float f1 = fmaxf(acc[mt][n8][half * 2 + 1] + P.views_b[col + 1], 0.f);
                const float* w0 = P.rgb_w + (size_t)col * 3;
                #pragma unroll
                for (int k = 0; k < 3; k++)
                    rp[mt][half][k] += f0 * w0[k] + f1 * w0[3 + k];
            }
    #pragma unroll
    for (int mt = 0; mt < 2; mt++)
        #pragma unroll
        for (int half = 0; half < 2; half++) {
            #pragma unroll
            for (int k = 0; k < 3; k++) {
                float v = rp[mt][half][k];
                v += __shfl_xor_sync(0xffffffffu, v, 1);
                v += __shfl_xor_sync(0xffffffffu, v, 2);
                rp[mt][half][k] = v;
            }
            if ((lane & 3) == 0) {
                uint32_t row = (uint32_t)(wm * 32 + mt * 16 + half * 8 + (lane >> 2));
                char* p = sm + PRGB + (row * 4 + wn) * 12;
                #pragma unroll
                for (int k = 0; k < 3; k++) *(float*)(p + k * 4) = rp[mt][half][k];
            }
        }
    __syncthreads();
    if (tid < 64) {
        float r[3] = {P.rgb_b[0], P.rgb_b[1], P.rgb_b[2]};
        char* p = sm + PRGB + (uint32_t)tid * 48;
        #pragma unroll
        for (int w = 0; w < 4; w++)
            #pragma unroll
            for (int k = 0; k < 3; k++) r[k] += *(float*)(p + w * 12 + k * 4);
        size_t gidx = (size_t)blk * 64 + tid;
        #pragma unroll
        for (int k = 0; k < 3; k++) P.out[(size_t)NPTS + gidx * 3 + k] = r[k];
    }
}

// ============================================================================
extern "C" void kernel_launch(void* const* d_in, const int* in_sizes, int n_in,
                              void* d_out, int out_size)
{
    (void)in_sizes; (void)n_in; (void)out_size;

    PrepP pp;
    for (int i = 0; i < 8; i++) pp.w[i] = (const float*)d_in[3 + 2 * i];
    pp.w[8] = (const float*)d_in[21];     // feature_w
    pp.w[9] = (const float*)d_in[19];     // views_w

    MainP P;
    P.input_pts   = (const float*)d_in[0];
    P.input_views = (const float*)d_in[1];
    P.input_pls   = (const float*)d_in[2];
    for (int i = 0; i < 8; i++) P.bias[i] = (const float*)d_in[4 + 2 * i];
    P.bias[8]  = (const float*)d_in[22];  // feature_b
    P.views_b  = (const float*)d_in[20];
    P.alpha_w  = (const float*)d_in[23];
    P.alpha_b  = (const float*)d_in[24];
    P.rgb_w    = (const float*)d_in[25];
    P.rgb_b    = (const float*)d_in[26];
    P.out      = (float*)d_out;

    prep_kernel<<<1320, 512>>>(pp);

    cudaFuncSetAttribute(nerf_hmma, cudaFuncAttributeMaxDynamicSharedMemorySize, SMEM_REQ);
    nerf_hmma<<<NBLK, NTH, SMEM_REQ>>>(P);
}